// round 8
// baseline (speedup 1.0000x reference)
#include <cuda_runtime.h>
#include <cuda_bf16.h>
#include <cstdint>

#define BB 32
#define NN 16384
#define CC 256
#define DD 64
#define SS 7
#define HH 128
#define MROWS (BB*NN)
#define SCALE_ATTN 0.125f
#define EPS_ATTN 1e-6f
#define LN_EPS 1e-5f
#define NCHUNK 16
#define CHUNK (NN/NCHUNK)
#define PART_STRIDE 456
#define APITCH 40   // bf16 row pitch (80B: 16B-aligned rows, conflict-free ldmatrix)

// proj smem layout (dynamic): two chunk buffers of [Ah|Al|Bh|Bl], each 128x40 bf16
#define PJ_BUF    40960
#define PJ_AL     10240
#define PJ_BH     20480
#define PJ_BL     30720
#define PJ_PARAMS 81920
#define PJ_SMEM   84992

// ---------------- scratch (static device globals; no allocation) ----------------
__device__ float g_K[MROWS*DD];
__device__ float g_V[MROWS*DD];
__device__ float g_q[BB*SS*DD];
__device__ float g_part[BB*NCHUNK*PART_STRIDE];
__device__ __nv_bfloat16 g_WbHi[128*256];
__device__ __nv_bfloat16 g_WbLo[128*256];

__device__ __forceinline__ float sigmoidf_(float x) { return 1.0f / (1.0f + __expf(-x)); }

__device__ __forceinline__ uint32_t smem_u32(const void* p) {
    uint32_t a;
    asm("{ .reg .u64 t; cvta.to.shared.u64 t, %1; cvt.u32.u64 %0, t; }" : "=r"(a) : "l"(p));
    return a;
}
__device__ __forceinline__ void mma16816(float* d, const uint32_t* a, const uint32_t* b) {
    asm volatile(
        "mma.sync.aligned.m16n8k16.row.col.f32.bf16.bf16.f32 "
        "{%0,%1,%2,%3}, {%4,%5,%6,%7}, {%8,%9}, {%0,%1,%2,%3};"
        : "+f"(d[0]), "+f"(d[1]), "+f"(d[2]), "+f"(d[3])
        : "r"(a[0]), "r"(a[1]), "r"(a[2]), "r"(a[3]), "r"(b[0]), "r"(b[1]));
}
__device__ __forceinline__ void ldsm_x4(uint32_t* r, uint32_t addr) {
    asm volatile("ldmatrix.sync.aligned.m8n8.x4.shared.b16 {%0,%1,%2,%3}, [%4];"
        : "=r"(r[0]), "=r"(r[1]), "=r"(r[2]), "=r"(r[3]) : "r"(addr));
}

// ---------------- kernel 0: init slot state into d_out ----------------
__global__ void init_slots_kernel(const float* __restrict__ mu, float* __restrict__ out) {
    int i = blockIdx.x * 256 + threadIdx.x;
    if (i < BB * SS * DD) out[i] = mu[i];
}

// ---------------- kernel 0b: split [Wk|Wv]^T into bf16 hi/lo, row-major [n][c] ----------------
__global__ void wsplit_kernel(const float* __restrict__ Wk, const float* __restrict__ Wv) {
    int idx = blockIdx.x * 256 + threadIdx.x;
    if (idx >= 128 * 256) return;
    int n = idx >> 8;
    int c = idx & 255;
    float w = (n < 64) ? Wk[c * 64 + n] : Wv[c * 64 + (n - 64)];
    __nv_bfloat16 hi = __float2bfloat16(w);
    __nv_bfloat16 lo = __float2bfloat16(w - __bfloat162float(hi));
    g_WbHi[n * 256 + c] = hi;
    g_WbLo[n * 256 + c] = lo;
}

// ---------------- kernel 1: LN + [K|V] projection via mma.sync bf16-split ----------------
__global__ void __launch_bounds__(256) proj_mma_kernel(
    const float* __restrict__ X,
    const float* __restrict__ lng, const float* __restrict__ lnb)
{
    extern __shared__ char smem[];
    float* s_mean = (float*)(smem + PJ_PARAMS);
    float* s_rstd = (float*)(smem + PJ_PARAMS + 512);
    float* s_g    = (float*)(smem + PJ_PARAMS + 1024);
    float* s_b    = (float*)(smem + PJ_PARAMS + 2048);

    const int tid = threadIdx.x, wid = tid >> 5, lane = tid & 31;
    const int m0 = blockIdx.x * 128;
    const uint32_t sbase = smem_u32(smem);

    s_g[tid] = lng[tid];
    s_b[tid] = lnb[tid];

    // ---- LN stats ----
    #pragma unroll 1
    for (int p = 0; p < 4; p++) {
        float sm[4], sq[4];
        #pragma unroll
        for (int i = 0; i < 4; i++) {
            int r = (p * 4 + i) * 8 + wid;
            const float* xr = X + (size_t)(m0 + r) * CC + lane * 8;
            float4 a  = *(const float4*)xr;
            float4 b4 = *(const float4*)(xr + 4);
            sm[i] = a.x + a.y + a.z + a.w + b4.x + b4.y + b4.z + b4.w;
            sq[i] = a.x*a.x + a.y*a.y + a.z*a.z + a.w*a.w
                  + b4.x*b4.x + b4.y*b4.y + b4.z*b4.z + b4.w*b4.w;
        }
        #pragma unroll
        for (int i = 0; i < 4; i++) {
            #pragma unroll
            for (int o = 16; o; o >>= 1) {
                sm[i] += __shfl_xor_sync(0xffffffffu, sm[i], o);
                sq[i] += __shfl_xor_sync(0xffffffffu, sq[i], o);
            }
            if (lane == 0) {
                int r = (p * 4 + i) * 8 + wid;
                float mu = sm[i] * (1.f / 256.f);
                s_mean[r] = mu;
                s_rstd[r] = rsqrtf(sq[i] * (1.f / 256.f) - mu * mu + LN_EPS);
            }
        }
    }
    __syncthreads();

    // loader roles
    const int r   = tid >> 1;
    const int seg = tid & 1;
    const float mu = s_mean[r], rs = s_rstd[r];
    const float* xrow = X + (size_t)(m0 + r) * CC + seg * 16;
    const __nv_bfloat16* wHrow = g_WbHi + r * 256 + seg * 16;
    const __nv_bfloat16* wLrow = g_WbLo + r * 256 + seg * 16;

    // mma roles
    const int mw = wid >> 1, nw = wid & 1;
    const int g  = lane >> 2, tg = lane & 3;
    const int mat = lane >> 3, rb = lane & 7;
    const uint32_t aoff = (uint32_t)((mw*32 + rb + (mat & 1)*8) * APITCH + (mat >> 1)*8) * 2;
    const uint32_t boff = (uint32_t)((nw*64 + rb) * APITCH + mat*8) * 2;

    float acc[2][8][4];
    #pragma unroll
    for (int mt = 0; mt < 2; mt++)
        #pragma unroll
        for (int nt = 0; nt < 8; nt++)
            #pragma unroll
            for (int e = 0; e < 4; e++) acc[mt][nt][e] = 0.f;

    float4 xv[4];
    uint4 bvh[2], bvl[2];

    // prologue: load chunk0 regs, stage buf0, load chunk1 regs
    #pragma unroll
    for (int i = 0; i < 4; i++) xv[i] = *(const float4*)(xrow + i * 4);
    bvh[0] = *(const uint4*)(wHrow);     bvh[1] = *(const uint4*)(wHrow + 8);
    bvl[0] = *(const uint4*)(wLrow);     bvl[1] = *(const uint4*)(wLrow + 8);

    {   // stage chunk 0 -> buf 0
        char* Ah = smem;            char* Al = smem + PJ_AL;
        char* Bh = smem + PJ_BH;    char* Bl = smem + PJ_BL;
        #pragma unroll
        for (int i = 0; i < 4; i++) {
            int cb = seg * 16 + i * 4;
            int c  = cb;
            float y0 = fmaf((xv[i].x - mu) * rs, s_g[c+0], s_b[c+0]);
            float y1 = fmaf((xv[i].y - mu) * rs, s_g[c+1], s_b[c+1]);
            float y2 = fmaf((xv[i].z - mu) * rs, s_g[c+2], s_b[c+2]);
            float y3 = fmaf((xv[i].w - mu) * rs, s_g[c+3], s_b[c+3]);
            __nv_bfloat162 h01 = __float22bfloat162_rn(make_float2(y0, y1));
            __nv_bfloat162 h23 = __float22bfloat162_rn(make_float2(y2, y3));
            __nv_bfloat162 l01 = __float22bfloat162_rn(make_float2(y0 - __low2float(h01), y1 - __high2float(h01)));
            __nv_bfloat162 l23 = __float22bfloat162_rn(make_float2(y2 - __low2float(h23), y3 - __high2float(h23)));
            uint2 uh = make_uint2(*(uint32_t*)&h01, *(uint32_t*)&h23);
            uint2 ul = make_uint2(*(uint32_t*)&l01, *(uint32_t*)&l23);
            *(uint2*)(Ah + r * 80 + cb * 2) = uh;
            *(uint2*)(Al + r * 80 + cb * 2) = ul;
        }
        *(uint4*)(Bh + r * 80 + seg * 32)      = bvh[0];
        *(uint4*)(Bh + r * 80 + seg * 32 + 16) = bvh[1];
        *(uint4*)(Bl + r * 80 + seg * 32)      = bvl[0];
        *(uint4*)(Bl + r * 80 + seg * 32 + 16) = bvl[1];
    }
    #pragma unroll
    for (int i = 0; i < 4; i++) xv[i] = *(const float4*)(xrow + 32 + i * 4);
    bvh[0] = *(const uint4*)(wHrow + 32); bvh[1] = *(const uint4*)(wHrow + 40);
    bvl[0] = *(const uint4*)(wLrow + 32); bvl[1] = *(const uint4*)(wLrow + 40);
    __syncthreads();

    #pragma unroll 1
    for (int kc = 0; kc < 8; kc++) {
        const uint32_t bufo = (uint32_t)(kc & 1) * PJ_BUF;

        // ---- stage chunk kc+1 into the other buffer (regs loaded last iter) ----
        if (kc < 7) {
            uint32_t nb = (uint32_t)((kc + 1) & 1) * PJ_BUF;
            char* Ah = smem + nb;            char* Al = smem + nb + PJ_AL;
            char* Bh = smem + nb + PJ_BH;    char* Bl = smem + nb + PJ_BL;
            #pragma unroll
            for (int i = 0; i < 4; i++) {
                int cb = seg * 16 + i * 4;
                int c  = (kc + 1) * 32 + cb;
                float y0 = fmaf((xv[i].x - mu) * rs, s_g[c+0], s_b[c+0]);
                float y1 = fmaf((xv[i].y - mu) * rs, s_g[c+1], s_b[c+1]);
                float y2 = fmaf((xv[i].z - mu) * rs, s_g[c+2], s_b[c+2]);
                float y3 = fmaf((xv[i].w - mu) * rs, s_g[c+3], s_b[c+3]);
                __nv_bfloat162 h01 = __float22bfloat162_rn(make_float2(y0, y1));
                __nv_bfloat162 h23 = __float22bfloat162_rn(make_float2(y2, y3));
                __nv_bfloat162 l01 = __float22bfloat162_rn(make_float2(y0 - __low2float(h01), y1 - __high2float(h01)));
                __nv_bfloat162 l23 = __float22bfloat162_rn(make_float2(y2 - __low2float(h23), y3 - __high2float(h23)));
                uint2 uh = make_uint2(*(uint32_t*)&h01, *(uint32_t*)&h23);
                uint2 ul = make_uint2(*(uint32_t*)&l01, *(uint32_t*)&l23);
                *(uint2*)(Ah + r * 80 + cb * 2) = uh;
                *(uint2*)(Al + r * 80 + cb * 2) = ul;
            }
            *(uint4*)(Bh + r * 80 + seg * 32)      = bvh[0];
            *(uint4*)(Bh + r * 80 + seg * 32 + 16) = bvh[1];
            *(uint4*)(Bl + r * 80 + seg * 32)      = bvl[0];
            *(uint4*)(Bl + r * 80 + seg * 32 + 16) = bvl[1];
        }
        // ---- prefetch chunk kc+2 from global ----
        if (kc < 6) {
            const float* xp = xrow + (kc + 2) * 32;
            #pragma unroll
            for (int i = 0; i < 4; i++) xv[i] = *(const float4*)(xp + i * 4);
            const __nv_bfloat16* wh = wHrow + (kc + 2) * 32;
            const __nv_bfloat16* wl = wLrow + (kc + 2) * 32;
            bvh[0] = *(const uint4*)(wh); bvh[1] = *(const uint4*)(wh + 8);
            bvl[0] = *(const uint4*)(wl); bvl[1] = *(const uint4*)(wl + 8);
        }

        // ---- MMA over current buffer via ldmatrix ----
        {
            const uint32_t aH = sbase + bufo + aoff;
            const uint32_t aL = aH + PJ_AL;
            const uint32_t bH = sbase + bufo + PJ_BH + boff;
            const uint32_t bL = bH + (PJ_BL - PJ_BH);

            uint32_t ah[2][2][4], al[2][2][4];
            #pragma unroll
            for (int mt = 0; mt < 2; mt++)
                #pragma unroll
                for (int ks = 0; ks < 2; ks++) {
                    ldsm_x4(ah[mt][ks], aH + mt * 1280 + ks * 32);
                    ldsm_x4(al[mt][ks], aL + mt * 1280 + ks * 32);
                }
            #pragma unroll
            for (int nt = 0; nt < 8; nt++) {
                uint32_t bh[4], bl[4];
                ldsm_x4(bh, bH + nt * 640);
                ldsm_x4(bl, bL + nt * 640);
                #pragma unroll
                for (int ks = 0; ks < 2; ks++) {
                    #pragma unroll
                    for (int mt = 0; mt < 2; mt++) {
                        mma16816(acc[mt][nt], ah[mt][ks], &bh[ks * 2]);
                        mma16816(acc[mt][nt], ah[mt][ks], &bl[ks * 2]);
                        mma16816(acc[mt][nt], al[mt][ks], &bh[ks * 2]);
                    }
                }
            }
        }
        __syncthreads();
    }

    // ---- epilogue ----
    float* dstbase = nw ? g_V : g_K;
    #pragma unroll
    for (int mt = 0; mt < 2; mt++) {
        int row0 = m0 + mw * 32 + mt * 16 + g;
        #pragma unroll
        for (int nt = 0; nt < 8; nt++) {
            int coll = nt * 8 + tg * 2;
            *(float2*)(dstbase + (size_t)row0 * DD + coll) =
                make_float2(acc[mt][nt][0], acc[mt][nt][1]);
            *(float2*)(dstbase + (size_t)(row0 + 8) * DD + coll) =
                make_float2(acc[mt][nt][2], acc[mt][nt][3]);
        }
    }
}

// ---------------- kernel 2: iteration-0 q projection ----------------
__global__ void __launch_bounds__(256) q_kernel(
    const float* __restrict__ slots,
    const float* __restrict__ qlg, const float* __restrict__ qlb,
    const float* __restrict__ Wq,
    const float* __restrict__ bqlg, const float* __restrict__ bqlb,
    const float* __restrict__ bWq)
{
    __shared__ float xs[8][64];
    const int tid = threadIdx.x, lane = tid & 31, ws = tid >> 5;
    const int wid = blockIdx.x * 8 + ws;
    const int m = wid % SS;

    const float* x = slots + wid * DD;
    float x0 = x[lane], x1 = x[lane + 32];
    float s = x0 + x1, q = x0 * x0 + x1 * x1;
    #pragma unroll
    for (int o = 16; o; o >>= 1) {
        s += __shfl_xor_sync(0xffffffffu, s, o);
        q += __shfl_xor_sync(0xffffffffu, q, o);
    }
    float mu = s * (1.f / 64.f);
    float rs = rsqrtf(q * (1.f / 64.f) - mu * mu + LN_EPS);

    const float* lg = (m < 6) ? qlg : bqlg;
    const float* lb = (m < 6) ? qlb : bqlb;
    const float* W  = (m < 6) ? Wq  : bWq;

    xs[ws][lane]      = (x0 - mu) * rs * lg[lane]      + lb[lane];
    xs[ws][lane + 32] = (x1 - mu) * rs * lg[lane + 32] + lb[lane + 32];
    __syncwarp();

    float q0 = 0.f, q1 = 0.f;
    #pragma unroll
    for (int e = 0; e < 64; e++) {
        float xe = xs[ws][e];
        q0 += xe * W[e * 64 + lane];
        q1 += xe * W[e * 64 + lane + 32];
    }
    g_q[wid * DD + lane]      = q0;
    g_q[wid * DD + lane + 32] = q1;
}

// ---------------- kernel 3: attention pass — 16 lanes/row, 2 rows/warp, 2-way n ILP ----------------
__global__ void __launch_bounds__(256, 2) attn_kernel(float* __restrict__ part)
{
    const int b = blockIdx.y;
    const int chunk = blockIdx.x;
    __shared__ float qs[SS * DD];
    __shared__ float Uw[8][PART_STRIDE];
    const int tid = threadIdx.x;
    for (int i = tid; i < SS * DD; i += 256) qs[i] = g_q[b * SS * DD + i];
    __syncthreads();

    const int lane = tid & 31, warp = tid >> 5;
    const int g = lane >> 4;
    const int j = lane & 15;

    float Up[SS][4];
    #pragma unroll
    for (int m = 0; m < SS; m++)
        #pragma unroll
        for (int e = 0; e < 4; e++) Up[m][e] = 0.f;
    float cs[SS] = {0.f, 0.f, 0.f, 0.f, 0.f, 0.f, 0.f};

    const float* Kb = g_K + (size_t)b * NN * DD;
    const float* Vb = g_V + (size_t)b * NN * DD;
    const int base = chunk * CHUNK + warp * 2 + g;

    #pragma unroll 1
    for (int s = 0; s < CHUNK / 32; s++) {
        int na = base + s * 16;
        int nb2 = na + (CHUNK / 2);
        float4 ka = __ldcs((const float4*)(Kb + (size_t)na * DD + j * 4));
        float4 va = __ldcs((const float4*)(Vb + (size_t)na * DD + j * 4));
        float4 kb = __ldcs((const float4*)(Kb + (size_t)nb2 * DD + j * 4));
        float4 vb = __ldcs((const float4*)(Vb + (size_t)nb2 * DD + j * 4));

        float la[SS], lb_[SS];
        #pragma unroll
        for (int m = 0; m < SS; m++) {
            float4 qm = *(const float4*)(qs + m * DD + j * 4);
            float pa = ka.x * qm.x + ka.y * qm.y + ka.z * qm.z + ka.w * qm.w;
            float pb = kb.x * qm.x + kb.y * qm.y + kb.z * qm.z + kb.w * qm.w;
            #pragma unroll
            for (int o = 1; o < 16; o <<= 1) {
                pa += __shfl_xor_sync(0xffffffffu, pa, o);
                pb += __shfl_xor_sync(0xffffffffu, pb, o);
            }
            la[m]  = pa * SCALE_ATTN;
            lb_[m] = pb * SCALE_ATTN;
        }
        float mxa = la[0], mxb = lb_[0];
        #pragma unroll
        for (int m = 1; m < SS; m++) { mxa = fmaxf(mxa, la[m]); mxb = fmaxf(mxb, lb_[m]); }
        float ea[SS], eb[SS], sa = 0.f, sb2 = 0.f;
        #pragma unroll
        for (int m = 0; m < SS; m++) {
            ea[m] = __expf(la[m] - mxa);  sa  += ea[m];
            eb[m] = __expf(lb_[m] - mxb); sb2 += eb[m];
        }
        float inva = 1.0f / sa, invb = 1.0f / sb2;
        #pragma unroll
        for (int m = 0; m < SS; m++) {
            float aa = ea[m] * inva + EPS_ATTN;
            float ab = eb[m] * invb + EPS_ATTN;
            cs[m] += aa + ab;
            Up[m][0] += aa * va.x + ab * vb.x;
            Up[m][1] += aa * va.y + ab * vb.y;
            Up[m][2] += aa * va.z + ab * vb.z;
            Up[m][3] += aa * va.w + ab * vb.w;
        }
    }

    #pragma unroll
    for (int m = 0; m < SS; m++) {
        #pragma unroll
        for (int e = 0; e < 4; e++) {
            float t = Up[m][e];
            t += __shfl_xor_sync(0xffffffffu, t, 16);
            Up[m][e] = t;
        }
        float c = cs[m];
        c += __shfl_xor_sync(0xffffffffu, c, 16);
        cs[m] = c;
    }
    if (lane < 16) {
        #pragma unroll
        for (int m = 0; m < SS; m++)
            #pragma unroll
            for (int e = 0; e < 4; e++)
                Uw[warp][m * DD + j * 4 + e] = Up[m][e];
    }
    if (lane == 0) {
        #pragma unroll
        for (int m = 0; m < SS; m++) Uw[warp][448 + m] = cs[m];
    }
    __syncthreads();

    float* dst = part + (size_t)(b * NCHUNK + chunk) * PART_STRIDE;
    for (int i = tid; i < 455; i += 256) {
        float acc = Uw[0][i];
        #pragma unroll
        for (int w = 1; w < 8; w++) acc += Uw[w][i];
        dst[i] = acc;
    }
}

// ---------------- kernel 4: slot update + fused next-iter q projection ----------------
__global__ void __launch_bounds__(128) update_kernel(
    float* __restrict__ slots,
    const float* __restrict__ Wih, const float* __restrict__ Whh,
    const float* __restrict__ bih, const float* __restrict__ bhh,
    const float* __restrict__ mlng, const float* __restrict__ mlnb,
    const float* __restrict__ mW1,  const float* __restrict__ mb1,
    const float* __restrict__ mW2,  const float* __restrict__ mb2,
    const float* __restrict__ bmlng, const float* __restrict__ bmlnb,
    const float* __restrict__ bmW1,  const float* __restrict__ bmb1,
    const float* __restrict__ bmW2,  const float* __restrict__ bmb2,
    const float* __restrict__ qlg, const float* __restrict__ qlb,
    const float* __restrict__ Wq,
    const float* __restrict__ bqlg, const float* __restrict__ bqlb,
    const float* __restrict__ bWq)
{
    const int b = blockIdx.y;
    const int s = blockIdx.x;
    const int t = threadIdx.x;

    __shared__ float us[64], hs[64], gi[192], gh[192], hn[64], xn[64], hid[128], fin[64], xq[64];
    __shared__ float red[2], red2[2];

    if (t < 64) {
        float ua = 0.f, ca = 0.f;
        #pragma unroll 1
        for (int c = 0; c < NCHUNK; c++) {
            const float* p = g_part + (size_t)(b * NCHUNK + c) * PART_STRIDE;
            ua += p[s * 64 + t];
            ca += p[448 + s];
        }
        us[t] = ua / ca;
        hs[t] = slots[(b * SS + s) * DD + t];
    }
    __syncthreads();

    for (int idx = t; idx < 384; idx += 128) {
        const bool isI = (idx < 192);
        const int oo = isI ? idx : (idx - 192);
        const float* W  = isI ? Wih : Whh;
        const float* xv = isI ? us : hs;
        float acc = isI ? bih[oo] : bhh[oo];
        #pragma unroll
        for (int e = 0; e < 64; e++) acc += xv[e] * W[oo * 64 + e];
        if (isI) gi[oo] = acc; else gh[oo] = acc;
    }
    __syncthreads();

    if (t < 64) {
        float r = sigmoidf_(gi[t] + gh[t]);
        float z = sigmoidf_(gi[64 + t] + gh[64 + t]);
        float n = tanhf(gi[128 + t] + r * gh[128 + t]);
        hn[t] = (1.0f - z) * n + z * hs[t];
    }
    __syncthreads();

    if (t < 32) {
        float a = hn[t], bv = hn[t + 32];
        float sm = a + bv, sq = a * a + bv * bv;
        #pragma unroll
        for (int o = 16; o; o >>= 1) {
            sm += __shfl_xor_sync(0xffffffffu, sm, o);
            sq += __shfl_xor_sync(0xffffffffu, sq, o);
        }
        if (t == 0) {
            float mu = sm * (1.f / 64.f);
            red[0] = mu;
            red[1] = rsqrtf(sq * (1.f / 64.f) - mu * mu + LN_EPS);
        }
    }
    __syncthreads();

    const float* lg = (s < 6) ? mlng : bmlng;
    const float* lb = (s < 6) ? mlnb : bmlnb;
    const float* W1 = (s < 6) ? mW1 : bmW1;
    const float* b1 = (s < 6) ? mb1 : bmb1;
    const float* W2 = (s < 6) ? mW2 : bmW2;
    const float* b2 = (s < 6) ? mb2 : bmb2;

    if (t < 64) xn[t] = (hn[t] - red[0]) * red[1] * lg[t] + lb[t];
    __syncthreads();

    {
        float h1 = b1[t];
        #pragma unroll
        for (int e = 0; e < 64; e++) h1 += xn[e] * W1[e * HH + t];
        hid[t] = fmaxf(h1, 0.f);
    }
    __syncthreads();

    if (t < 64) {
        float o = b2[t];
        #pragma unroll
        for (int jj = 0; jj < 128; jj++) o += hid[jj] * W2[jj * 64 + t];
        float fv = hn[t] + o;
        slots[(b * SS + s) * DD + t] = fv;
        fin[t] = fv;
    }
    __syncthreads();

    // ---- fused q projection for next iteration ----
    if (t < 32) {
        float a = fin[t], bv = fin[t + 32];
        float sm = a + bv, sq = a * a + bv * bv;
        #pragma unroll
        for (int o = 16; o; o >>= 1) {
            sm += __shfl_xor_sync(0xffffffffu, sm, o);
            sq += __shfl_xor_sync(0xffffffffu, sq, o);
        }
        if (t == 0) {
            float mu = sm * (1.f / 64.f);
            red2[0] = mu;
            red2[1] = rsqrtf(sq * (1.f / 64.f) - mu * mu + LN_EPS);
        }
    }
    __syncthreads();

    const float* qg = (s < 6) ? qlg : bqlg;
    const float* qb = (s < 6) ? qlb : bqlb;
    const float* qW = (s < 6) ? Wq  : bWq;

    if (t < 64) xq[t] = (fin[t] - red2[0]) * red2[1] * qg[t] + qb[t];
    __syncthreads();

    if (t < 64) {
        float qv = 0.f;
        #pragma unroll
        for (int e = 0; e < 64; e++) qv += xq[e] * qW[e * 64 + t];
        g_q[(b * SS + s) * DD + t] = qv;
    }
}

// ---------------- launcher ----------------
extern "C" void kernel_launch(void* const* d_in, const int* in_sizes, int n_in,
                              void* d_out, int out_size) {
    (void)in_sizes; (void)n_in; (void)out_size;
    const float* inputs   = (const float*)d_in[0];
    const float* slots_mu = (const float*)d_in[1];
    const float* ln_in_g  = (const float*)d_in[2];
    const float* ln_in_b  = (const float*)d_in[3];
    const float* Wk       = (const float*)d_in[4];
    const float* Wv       = (const float*)d_in[5];
    const float* q_ln_g   = (const float*)d_in[6];
    const float* q_ln_b   = (const float*)d_in[7];
    const float* Wq       = (const float*)d_in[8];
    const float* bq_ln_g  = (const float*)d_in[9];
    const float* bq_ln_b  = (const float*)d_in[10];
    const float* bWq      = (const float*)d_in[11];
    const float* gWih     = (const float*)d_in[12];
    const float* gWhh     = (const float*)d_in[13];
    const float* gbih     = (const float*)d_in[14];
    const float* gbhh     = (const float*)d_in[15];
    const float* mlng     = (const float*)d_in[16];
    const float* mlnb     = (const float*)d_in[17];
    const float* mW1      = (const float*)d_in[18];
    const float* mb1      = (const float*)d_in[19];
    const float* mW2      = (const float*)d_in[20];
    const float* mb2      = (const float*)d_in[21];
    const float* bmlng    = (const float*)d_in[22];
    const float* bmlnb    = (const float*)d_in[23];
    const float* bmW1     = (const float*)d_in[24];
    const float* bmb1     = (const float*)d_in[25];
    const float* bmW2     = (const float*)d_in[26];
    const float* bmb2     = (const float*)d_in[27];
    float* out = (float*)d_out;

    float* part;
    cudaGetSymbolAddress((void**)&part, g_part);

    cudaFuncSetAttribute(proj_mma_kernel,
                         cudaFuncAttributeMaxDynamicSharedMemorySize, PJ_SMEM);

    init_slots_kernel<<<56, 256>>>(slots_mu, out);
    wsplit_kernel<<<128, 256>>>(Wk, Wv);
    proj_mma_kernel<<<MROWS / 128, 256, PJ_SMEM>>>(inputs, ln_in_g, ln_in_b);
    q_kernel<<<28, 256>>>(out, q_ln_g, q_ln_b, Wq, bq_ln_g, bq_ln_b, bWq);

    for (int it = 0; it < 3; it++) {
        attn_kernel<<<dim3(NCHUNK, BB), 256>>>(part);
        update_kernel<<<dim3(SS, BB), 128>>>(out, gWih, gWhh, gbih, gbhh,
                                             mlng, mlnb, mW1, mb1, mW2, mb2,
                                             bmlng, bmlnb, bmW1, bmb1, bmW2, bmb2,
                                             q_ln_g, q_ln_b, Wq, bq_ln_g, bq_ln_b, bWq);
    }
}

// round 11
// speedup vs baseline: 1.1119x; 1.1119x over previous
#include <cuda_runtime.h>
#include <cuda_bf16.h>
#include <cuda_fp16.h>
#include <cstdint>

#define BB 32
#define NN 16384
#define CC 256
#define DD 64
#define SS 7
#define HH 128
#define MROWS (BB*NN)
#define SCALE_ATTN 0.125f
#define EPS_ATTN 1e-6f
#define LN_EPS 1e-5f
#define NCHUNK 16
#define CHUNK (NN/NCHUNK)
#define PART_STRIDE 456
#define APITCH 40   // fp16 row pitch (80B: 16B-aligned rows, conflict-free ldmatrix)

// proj smem layout (dynamic): two chunk buffers of [Ah|Al|Bh], each 128x40 fp16
#define PJ_AL     10240
#define PJ_BH     20480
#define PJ_BUF    30720
#define PJ_PARAMS 61440
#define PJ_SMEM   64512

// ---------------- scratch (static device globals; no allocation) ----------------
__device__ float g_K[MROWS*DD];
__device__ float g_V[MROWS*DD];
__device__ float g_q[BB*SS*DD];
__device__ float g_part[BB*NCHUNK*PART_STRIDE];
__device__ __half g_WbH[128*256];   // fp16 weights, row-major [n][c]

__device__ __forceinline__ float sigmoidf_(float x) { return 1.0f / (1.0f + __expf(-x)); }

__device__ __forceinline__ uint32_t smem_u32(const void* p) {
    uint32_t a;
    asm("{ .reg .u64 t; cvta.to.shared.u64 t, %1; cvt.u32.u64 %0, t; }" : "=r"(a) : "l"(p));
    return a;
}
__device__ __forceinline__ void mma16816(float* d, const uint32_t* a, const uint32_t* b) {
    asm volatile(
        "mma.sync.aligned.m16n8k16.row.col.f32.f16.f16.f32 "
        "{%0,%1,%2,%3}, {%4,%5,%6,%7}, {%8,%9}, {%0,%1,%2,%3};"
        : "+f"(d[0]), "+f"(d[1]), "+f"(d[2]), "+f"(d[3])
        : "r"(a[0]), "r"(a[1]), "r"(a[2]), "r"(a[3]), "r"(b[0]), "r"(b[1]));
}
__device__ __forceinline__ void ldsm_x4(uint32_t* r, uint32_t addr) {
    asm volatile("ldmatrix.sync.aligned.m8n8.x4.shared.b16 {%0,%1,%2,%3}, [%4];"
        : "=r"(r[0]), "=r"(r[1]), "=r"(r[2]), "=r"(r[3]) : "r"(addr));
}

// ---------------- kernel 0: init slot state into d_out ----------------
__global__ void init_slots_kernel(const float* __restrict__ mu, float* __restrict__ out) {
    int i = blockIdx.x * 256 + threadIdx.x;
    if (i < BB * SS * DD) out[i] = mu[i];
}

// ---------------- kernel 0b: [Wk|Wv]^T -> fp16, row-major [n][c] ----------------
__global__ void wsplit_kernel(const float* __restrict__ Wk, const float* __restrict__ Wv) {
    int idx = blockIdx.x * 256 + threadIdx.x;
    if (idx >= 128 * 256) return;
    int n = idx >> 8;
    int c = idx & 255;
    float w = (n < 64) ? Wk[c * 64 + n] : Wv[c * 64 + (n - 64)];
    g_WbH[n * 256 + c] = __float2half_rn(w);
}

// ---------------- kernel 2: iteration-0 q projection ----------------
__global__ void __launch_bounds__(256) q_kernel(
    const float* __restrict__ slots,
    const float* __restrict__ qlg, const float* __restrict__ qlb,
    const float* __restrict__ Wq,
    const float* __restrict__ bqlg, const float* __restrict__ bqlb,
    const float* __restrict__ bWq)
{
    __shared__ float xs[8][64];
    const int tid = threadIdx.x, lane = tid & 31, ws = tid >> 5;
    const int wid = blockIdx.x * 8 + ws;
    const int m = wid % SS;

    const float* x = slots + wid * DD;
    float x0 = x[lane], x1 = x[lane + 32];
    float s = x0 + x1, q = x0 * x0 + x1 * x1;
    #pragma unroll
    for (int o = 16; o; o >>= 1) {
        s += __shfl_xor_sync(0xffffffffu, s, o);
        q += __shfl_xor_sync(0xffffffffu, q, o);
    }
    float mu = s * (1.f / 64.f);
    float rs = rsqrtf(q * (1.f / 64.f) - mu * mu + LN_EPS);

    const float* lg = (m < 6) ? qlg : bqlg;
    const float* lb = (m < 6) ? qlb : bqlb;
    const float* W  = (m < 6) ? Wq  : bWq;

    xs[ws][lane]      = (x0 - mu) * rs * lg[lane]      + lb[lane];
    xs[ws][lane + 32] = (x1 - mu) * rs * lg[lane + 32] + lb[lane + 32];
    __syncwarp();

    float q0 = 0.f, q1 = 0.f;
    #pragma unroll
    for (int e = 0; e < 64; e++) {
        float xe = xs[ws][e];
        q0 += xe * W[e * 64 + lane];
        q1 += xe * W[e * 64 + lane + 32];
    }
    g_q[wid * DD + lane]      = q0;
    g_q[wid * DD + lane + 32] = q1;
}

// ---------------- kernel 1: LN + [K|V] projection, fp16-split 2-pass mma.sync ----------------
__global__ void __launch_bounds__(256) proj_mma_kernel(
    const float* __restrict__ X,
    const float* __restrict__ lng, const float* __restrict__ lnb)
{
    extern __shared__ char smem[];
    float* s_mean = (float*)(smem + PJ_PARAMS);
    float* s_rstd = (float*)(smem + PJ_PARAMS + 512);
    float* s_g    = (float*)(smem + PJ_PARAMS + 1024);
    float* s_b    = (float*)(smem + PJ_PARAMS + 2048);

    const int tid = threadIdx.x, wid = tid >> 5, lane = tid & 31;
    const int m0 = blockIdx.x * 128;
    const uint32_t sbase = smem_u32(smem);

    s_g[tid] = lng[tid];
    s_b[tid] = lnb[tid];

    // ---- LN stats ----
    #pragma unroll 1
    for (int p = 0; p < 4; p++) {
        float sm[4], sq[4];
        #pragma unroll
        for (int i = 0; i < 4; i++) {
            int r = (p * 4 + i) * 8 + wid;
            const float* xr = X + (size_t)(m0 + r) * CC + lane * 8;
            float4 a  = *(const float4*)xr;
            float4 b4 = *(const float4*)(xr + 4);
            sm[i] = a.x + a.y + a.z + a.w + b4.x + b4.y + b4.z + b4.w;
            sq[i] = a.x*a.x + a.y*a.y + a.z*a.z + a.w*a.w
                  + b4.x*b4.x + b4.y*b4.y + b4.z*b4.z + b4.w*b4.w;
        }
        #pragma unroll
        for (int i = 0; i < 4; i++) {
            #pragma unroll
            for (int o = 16; o; o >>= 1) {
                sm[i] += __shfl_xor_sync(0xffffffffu, sm[i], o);
                sq[i] += __shfl_xor_sync(0xffffffffu, sq[i], o);
            }
            if (lane == 0) {
                int r = (p * 4 + i) * 8 + wid;
                float mu = sm[i] * (1.f / 256.f);
                s_mean[r] = mu;
                s_rstd[r] = rsqrtf(sq[i] * (1.f / 256.f) - mu * mu + LN_EPS);
            }
        }
    }
    __syncthreads();

    // loader roles
    const int r   = tid >> 1;
    const int seg = tid & 1;
    const float mu = s_mean[r], rs = s_rstd[r];
    const float* xrow = X + (size_t)(m0 + r) * CC + seg * 16;
    const __half* wHrow = g_WbH + r * 256 + seg * 16;

    // mma roles
    const int mw = wid >> 1, nw = wid & 1;
    const int g  = lane >> 2, tg = lane & 3;
    const int mat = lane >> 3, rb = lane & 7;
    const uint32_t aoff = (uint32_t)((mw*32 + rb + (mat & 1)*8) * APITCH + (mat >> 1)*8) * 2;
    const uint32_t boff = (uint32_t)((nw*64 + rb) * APITCH + mat*8) * 2;

    float acc[2][8][4];
    #pragma unroll
    for (int mt = 0; mt < 2; mt++)
        #pragma unroll
        for (int nt = 0; nt < 8; nt++)
            #pragma unroll
            for (int e = 0; e < 4; e++) acc[mt][nt][e] = 0.f;

    float4 xv[4];
    uint4 bvh[2];

    // prologue: load chunk0 regs, stage buf0, load chunk1 regs
    #pragma unroll
    for (int i = 0; i < 4; i++) xv[i] = *(const float4*)(xrow + i * 4);
    bvh[0] = *(const uint4*)(wHrow);
    bvh[1] = *(const uint4*)(wHrow + 8);

    {   // stage chunk 0 -> buf 0
        char* Ah = smem;            char* Al = smem + PJ_AL;
        char* Bh = smem + PJ_BH;
        #pragma unroll
        for (int i = 0; i < 4; i++) {
            int cb = seg * 16 + i * 4;
            int c  = cb;
            float y0 = fmaf((xv[i].x - mu) * rs, s_g[c+0], s_b[c+0]);
            float y1 = fmaf((xv[i].y - mu) * rs, s_g[c+1], s_b[c+1]);
            float y2 = fmaf((xv[i].z - mu) * rs, s_g[c+2], s_b[c+2]);
            float y3 = fmaf((xv[i].w - mu) * rs, s_g[c+3], s_b[c+3]);
            __half2 h01 = __float22half2_rn(make_float2(y0, y1));
            __half2 h23 = __float22half2_rn(make_float2(y2, y3));
            float2 r01 = __half22float2(h01);
            float2 r23 = __half22float2(h23);
            __half2 l01 = __float22half2_rn(make_float2(y0 - r01.x, y1 - r01.y));
            __half2 l23 = __float22half2_rn(make_float2(y2 - r23.x, y3 - r23.y));
            uint2 uh = make_uint2(*(uint32_t*)&h01, *(uint32_t*)&h23);
            uint2 ul = make_uint2(*(uint32_t*)&l01, *(uint32_t*)&l23);
            *(uint2*)(Ah + r * 80 + cb * 2) = uh;
            *(uint2*)(Al + r * 80 + cb * 2) = ul;
        }
        *(uint4*)(Bh + r * 80 + seg * 32)      = bvh[0];
        *(uint4*)(Bh + r * 80 + seg * 32 + 16) = bvh[1];
    }
    #pragma unroll
    for (int i = 0; i < 4; i++) xv[i] = *(const float4*)(xrow + 32 + i * 4);
    bvh[0] = *(const uint4*)(wHrow + 32);
    bvh[1] = *(const uint4*)(wHrow + 40);
    __syncthreads();

    #pragma unroll 1
    for (int kc = 0; kc < 8; kc++) {
        const uint32_t bufo = (uint32_t)(kc & 1) * PJ_BUF;

        // ---- stage chunk kc+1 into the other buffer (regs loaded last iter) ----
        if (kc < 7) {
            uint32_t nb = (uint32_t)((kc + 1) & 1) * PJ_BUF;
            char* Ah = smem + nb;            char* Al = smem + nb + PJ_AL;
            char* Bh = smem + nb + PJ_BH;
            #pragma unroll
            for (int i = 0; i < 4; i++) {
                int cb = seg * 16 + i * 4;
                int c  = (kc + 1) * 32 + cb;
                float y0 = fmaf((xv[i].x - mu) * rs, s_g[c+0], s_b[c+0]);
                float y1 = fmaf((xv[i].y - mu) * rs, s_g[c+1], s_b[c+1]);
                float y2 = fmaf((xv[i].z - mu) * rs, s_g[c+2], s_b[c+2]);
                float y3 = fmaf((xv[i].w - mu) * rs, s_g[c+3], s_b[c+3]);
                __half2 h01 = __float22half2_rn(make_float2(y0, y1));
                __half2 h23 = __float22half2_rn(make_float2(y2, y3));
                float2 r01 = __half22float2(h01);
                float2 r23 = __half22float2(h23);
                __half2 l01 = __float22half2_rn(make_float2(y0 - r01.x, y1 - r01.y));
                __half2 l23 = __float22half2_rn(make_float2(y2 - r23.x, y3 - r23.y));
                uint2 uh = make_uint2(*(uint32_t*)&h01, *(uint32_t*)&h23);
                uint2 ul = make_uint2(*(uint32_t*)&l01, *(uint32_t*)&l23);
                *(uint2*)(Ah + r * 80 + cb * 2) = uh;
                *(uint2*)(Al + r * 80 + cb * 2) = ul;
            }
            *(uint4*)(Bh + r * 80 + seg * 32)      = bvh[0];
            *(uint4*)(Bh + r * 80 + seg * 32 + 16) = bvh[1];
        }
        // ---- prefetch chunk kc+2 from global ----
        if (kc < 6) {
            const float* xp = xrow + (kc + 2) * 32;
            #pragma unroll
            for (int i = 0; i < 4; i++) xv[i] = *(const float4*)(xp + i * 4);
            const __half* wh = wHrow + (kc + 2) * 32;
            bvh[0] = *(const uint4*)(wh);
            bvh[1] = *(const uint4*)(wh + 8);
        }

        // ---- MMA over current buffer via ldmatrix: 2 passes (Ah + Al) x Bh ----
        {
            const uint32_t aH = sbase + bufo + aoff;
            const uint32_t aL = aH + PJ_AL;
            const uint32_t bH = sbase + bufo + PJ_BH + boff;

            uint32_t ah[2][2][4], al[2][2][4];
            #pragma unroll
            for (int mt = 0; mt < 2; mt++)
                #pragma unroll
                for (int ks = 0; ks < 2; ks++) {
                    ldsm_x4(ah[mt][ks], aH + mt * 1280 + ks * 32);
                    ldsm_x4(al[mt][ks], aL + mt * 1280 + ks * 32);
                }
            #pragma unroll
            for (int nt = 0; nt < 8; nt++) {
                uint32_t bh[4];
                ldsm_x4(bh, bH + nt * 640);
                #pragma unroll
                for (int ks = 0; ks < 2; ks++) {
                    #pragma unroll
                    for (int mt = 0; mt < 2; mt++) {
                        mma16816(acc[mt][nt], ah[mt][ks], &bh[ks * 2]);
                        mma16816(acc[mt][nt], al[mt][ks], &bh[ks * 2]);
                    }
                }
            }
        }
        __syncthreads();
    }

    // ---- epilogue ----
    float* dstbase = nw ? g_V : g_K;
    #pragma unroll
    for (int mt = 0; mt < 2; mt++) {
        int row0 = m0 + mw * 32 + mt * 16 + g;
        #pragma unroll
        for (int nt = 0; nt < 8; nt++) {
            int coll = nt * 8 + tg * 2;
            *(float2*)(dstbase + (size_t)row0 * DD + coll) =
                make_float2(acc[mt][nt][0], acc[mt][nt][1]);
            *(float2*)(dstbase + (size_t)(row0 + 8) * DD + coll) =
                make_float2(acc[mt][nt][2], acc[mt][nt][3]);
        }
    }
}

// ---------------- kernel 3: attention pass — 16 lanes/row, 2 rows/warp, 2-way n ILP ----------------
__global__ void __launch_bounds__(256, 2) attn_kernel(float* __restrict__ part)
{
    const int b = blockIdx.y;
    const int chunk = blockIdx.x;
    __shared__ float qs[SS * DD];
    __shared__ float Uw[8][PART_STRIDE];
    const int tid = threadIdx.x;
    for (int i = tid; i < SS * DD; i += 256) qs[i] = g_q[b * SS * DD + i];
    __syncthreads();

    const int lane = tid & 31, warp = tid >> 5;
    const int g = lane >> 4;
    const int j = lane & 15;

    float Up[SS][4];
    #pragma unroll
    for (int m = 0; m < SS; m++)
        #pragma unroll
        for (int e = 0; e < 4; e++) Up[m][e] = 0.f;
    float cs[SS] = {0.f, 0.f, 0.f, 0.f, 0.f, 0.f, 0.f};

    const float* Kb = g_K + (size_t)b * NN * DD;
    const float* Vb = g_V + (size_t)b * NN * DD;
    const int base = chunk * CHUNK + warp * 2 + g;

    #pragma unroll 1
    for (int s = 0; s < CHUNK / 32; s++) {
        int na = base + s * 16;
        int nb2 = na + (CHUNK / 2);
        float4 ka = __ldcs((const float4*)(Kb + (size_t)na * DD + j * 4));
        float4 va = __ldcs((const float4*)(Vb + (size_t)na * DD + j * 4));
        float4 kb = __ldcs((const float4*)(Kb + (size_t)nb2 * DD + j * 4));
        float4 vb = __ldcs((const float4*)(Vb + (size_t)nb2 * DD + j * 4));

        float la[SS], lb_[SS];
        #pragma unroll
        for (int m = 0; m < SS; m++) {
            float4 qm = *(const float4*)(qs + m * DD + j * 4);
            float pa = ka.x * qm.x + ka.y * qm.y + ka.z * qm.z + ka.w * qm.w;
            float pb = kb.x * qm.x + kb.y * qm.y + kb.z * qm.z + kb.w * qm.w;
            #pragma unroll
            for (int o = 1; o < 16; o <<= 1) {
                pa += __shfl_xor_sync(0xffffffffu, pa, o);
                pb += __shfl_xor_sync(0xffffffffu, pb, o);
            }
            la[m]  = pa * SCALE_ATTN;
            lb_[m] = pb * SCALE_ATTN;
        }
        float mxa = la[0], mxb = lb_[0];
        #pragma unroll
        for (int m = 1; m < SS; m++) { mxa = fmaxf(mxa, la[m]); mxb = fmaxf(mxb, lb_[m]); }
        float ea[SS], eb[SS], sa = 0.f, sb2 = 0.f;
        #pragma unroll
        for (int m = 0; m < SS; m++) {
            ea[m] = __expf(la[m] - mxa);  sa  += ea[m];
            eb[m] = __expf(lb_[m] - mxb); sb2 += eb[m];
        }
        float inva = 1.0f / sa, invb = 1.0f / sb2;
        #pragma unroll
        for (int m = 0; m < SS; m++) {
            float aa = ea[m] * inva + EPS_ATTN;
            float ab = eb[m] * invb + EPS_ATTN;
            cs[m] += aa + ab;
            Up[m][0] += aa * va.x + ab * vb.x;
            Up[m][1] += aa * va.y + ab * vb.y;
            Up[m][2] += aa * va.z + ab * vb.z;
            Up[m][3] += aa * va.w + ab * vb.w;
        }
    }

    #pragma unroll
    for (int m = 0; m < SS; m++) {
        #pragma unroll
        for (int e = 0; e < 4; e++) {
            float t = Up[m][e];
            t += __shfl_xor_sync(0xffffffffu, t, 16);
            Up[m][e] = t;
        }
        float c = cs[m];
        c += __shfl_xor_sync(0xffffffffu, c, 16);
        cs[m] = c;
    }
    if (lane < 16) {
        #pragma unroll
        for (int m = 0; m < SS; m++)
            #pragma unroll
            for (int e = 0; e < 4; e++)
                Uw[warp][m * DD + j * 4 + e] = Up[m][e];
    }
    if (lane == 0) {
        #pragma unroll
        for (int m = 0; m < SS; m++) Uw[warp][448 + m] = cs[m];
    }
    __syncthreads();

    float* dst = part + (size_t)(b * NCHUNK + chunk) * PART_STRIDE;
    for (int i = tid; i < 455; i += 256) {
        float acc = Uw[0][i];
        #pragma unroll
        for (int w = 1; w < 8; w++) acc += Uw[w][i];
        dst[i] = acc;
    }
}

// ---------------- kernel 4: slot update + fused next-iter q projection ----------------
__global__ void __launch_bounds__(128) update_kernel(
    float* __restrict__ slots,
    const float* __restrict__ Wih, const float* __restrict__ Whh,
    const float* __restrict__ bih, const float* __restrict__ bhh,
    const float* __restrict__ mlng, const float* __restrict__ mlnb,
    const float* __restrict__ mW1,  const float* __restrict__ mb1,
    const float* __restrict__ mW2,  const float* __restrict__ mb2,
    const float* __restrict__ bmlng, const float* __restrict__ bmlnb,
    const float* __restrict__ bmW1,  const float* __restrict__ bmb1,
    const float* __restrict__ bmW2,  const float* __restrict__ bmb2,
    const float* __restrict__ qlg, const float* __restrict__ qlb,
    const float* __restrict__ Wq,
    const float* __restrict__ bqlg, const float* __restrict__ bqlb,
    const float* __restrict__ bWq)
{
    const int b = blockIdx.y;
    const int s = blockIdx.x;
    const int t = threadIdx.x;

    __shared__ float us[64], hs[64], gi[192], gh[192], hn[64], xn[64], hid[128], fin[64], xq[64];
    __shared__ float red[2], red2[2];

    if (t < 64) {
        float ua = 0.f, ca = 0.f;
        #pragma unroll 1
        for (int c = 0; c < NCHUNK; c++) {
            const float* p = g_part + (size_t)(b * NCHUNK + c) * PART_STRIDE;
            ua += p[s * 64 + t];
            ca += p[448 + s];
        }
        us[t] = ua / ca;
        hs[t] = slots[(b * SS + s) * DD + t];
    }
    __syncthreads();

    for (int idx = t; idx < 384; idx += 128) {
        const bool isI = (idx < 192);
        const int oo = isI ? idx : (idx - 192);
        const float* W  = isI ? Wih : Whh;
        const float* xv = isI ? us : hs;
        float acc = isI ? bih[oo] : bhh[oo];
        #pragma unroll
        for (int e = 0; e < 64; e++) acc += xv[e] * W[oo * 64 + e];
        if (isI) gi[oo] = acc; else gh[oo] = acc;
    }
    __syncthreads();

    if (t < 64) {
        float r = sigmoidf_(gi[t] + gh[t]);
        float z = sigmoidf_(gi[64 + t] + gh[64 + t]);
        float n = tanhf(gi[128 + t] + r * gh[128 + t]);
        hn[t] = (1.0f - z) * n + z * hs[t];
    }
    __syncthreads();

    if (t < 32) {
        float a = hn[t], bv = hn[t + 32];
        float sm = a + bv, sq = a * a + bv * bv;
        #pragma unroll
        for (int o = 16; o; o >>= 1) {
            sm += __shfl_xor_sync(0xffffffffu, sm, o);
            sq += __shfl_xor_sync(0xffffffffu, sq, o);
        }
        if (t == 0) {
            float mu = sm * (1.f / 64.f);
            red[0] = mu;
            red[1] = rsqrtf(sq * (1.f / 64.f) - mu * mu + LN_EPS);
        }
    }
    __syncthreads();

    const float* lg = (s < 6) ? mlng : bmlng;
    const float* lb = (s < 6) ? mlnb : bmlnb;
    const float* W1 = (s < 6) ? mW1 : bmW1;
    const float* b1 = (s < 6) ? mb1 : bmb1;
    const float* W2 = (s < 6) ? mW2 : bmW2;
    const float* b2 = (s < 6) ? mb2 : bmb2;

    if (t < 64) xn[t] = (hn[t] - red[0]) * red[1] * lg[t] + lb[t];
    __syncthreads();

    {
        float h1 = b1[t];
        #pragma unroll
        for (int e = 0; e < 64; e++) h1 += xn[e] * W1[e * HH + t];
        hid[t] = fmaxf(h1, 0.f);
    }
    __syncthreads();

    if (t < 64) {
        float o = b2[t];
        #pragma unroll
        for (int jj = 0; jj < 128; jj++) o += hid[jj] * W2[jj * 64 + t];
        float fv = hn[t] + o;
        slots[(b * SS + s) * DD + t] = fv;
        fin[t] = fv;
    }
    __syncthreads();

    // ---- fused q projection for next iteration ----
    if (t < 32) {
        float a = fin[t], bv = fin[t + 32];
        float sm = a + bv, sq = a * a + bv * bv;
        #pragma unroll
        for (int o = 16; o; o >>= 1) {
            sm += __shfl_xor_sync(0xffffffffu, sm, o);
            sq += __shfl_xor_sync(0xffffffffu, sq, o);
        }
        if (t == 0) {
            float mu = sm * (1.f / 64.f);
            red2[0] = mu;
            red2[1] = rsqrtf(sq * (1.f / 64.f) - mu * mu + LN_EPS);
        }
    }
    __syncthreads();

    const float* qg = (s < 6) ? qlg : bqlg;
    const float* qb = (s < 6) ? qlb : bqlb;
    const float* qW = (s < 6) ? Wq  : bWq;

    if (t < 64) xq[t] = (fin[t] - red2[0]) * red2[1] * qg[t] + qb[t];
    __syncthreads();

    if (t < 64) {
        float qv = 0.f;
        #pragma unroll
        for (int e = 0; e < 64; e++) qv += xq[e] * qW[e * 64 + t];
        g_q[(b * SS + s) * DD + t] = qv;
    }
}

// ---------------- launcher ----------------
extern "C" void kernel_launch(void* const* d_in, const int* in_sizes, int n_in,
                              void* d_out, int out_size) {
    (void)in_sizes; (void)n_in; (void)out_size;
    const float* inputs   = (const float*)d_in[0];
    const float* slots_mu = (const float*)d_in[1];
    const float* ln_in_g  = (const float*)d_in[2];
    const float* ln_in_b  = (const float*)d_in[3];
    const float* Wk       = (const float*)d_in[4];
    const float* Wv       = (const float*)d_in[5];
    const float* q_ln_g   = (const float*)d_in[6];
    const float* q_ln_b   = (const float*)d_in[7];
    const float* Wq       = (const float*)d_in[8];
    const float* bq_ln_g  = (const float*)d_in[9];
    const float* bq_ln_b  = (const float*)d_in[10];
    const float* bWq      = (const float*)d_in[11];
    const float* gWih     = (const float*)d_in[12];
    const float* gWhh     = (const float*)d_in[13];
    const float* gbih     = (const float*)d_in[14];
    const float* gbhh     = (const float*)d_in[15];
    const float* mlng     = (const float*)d_in[16];
    const float* mlnb     = (const float*)d_in[17];
    const float* mW1      = (const float*)d_in[18];
    const float* mb1      = (const float*)d_in[19];
    const float* mW2      = (const float*)d_in[20];
    const float* mb2      = (const float*)d_in[21];
    const float* bmlng    = (const float*)d_in[22];
    const float* bmlnb    = (const float*)d_in[23];
    const float* bmW1     = (const float*)d_in[24];
    const float* bmb1     = (const float*)d_in[25];
    const float* bmW2     = (const float*)d_in[26];
    const float* bmb2     = (const float*)d_in[27];
    float* out = (float*)d_out;

    float* part;
    cudaGetSymbolAddress((void**)&part, g_part);

    cudaFuncSetAttribute(proj_mma_kernel,
                         cudaFuncAttributeMaxDynamicSharedMemorySize, PJ_SMEM);

    // order chosen so the ncu fixed-index capture lands on proj_mma_kernel
    init_slots_kernel<<<56, 256>>>(slots_mu, out);
    wsplit_kernel<<<128, 256>>>(Wk, Wv);
    q_kernel<<<28, 256>>>(out, q_ln_g, q_ln_b, Wq, bq_ln_g, bq_ln_b, bWq);
    proj_mma_kernel<<<MROWS / 128, 256, PJ_SMEM>>>(inputs, ln_in_g, ln_in_b);

    for (int it = 0; it < 3; it++) {
        attn_kernel<<<dim3(NCHUNK, BB), 256>>>(part);
        update_kernel<<<dim3(SS, BB), 128>>>(out, gWih, gWhh, gbih, gbhh,
                                             mlng, mlnb, mW1, mb1, mW2, mb2,
                                             bmlng, bmlnb, bmW1, bmb1, bmW2, bmb2,
                                             q_ln_g, q_ln_b, Wq, bq_ln_g, bq_ln_b, bWq);
    }
}

// round 12
// speedup vs baseline: 1.4596x; 1.3126x over previous
#include <cuda_runtime.h>
#include <cuda_fp16.h>
#include <cstdint>

#define BB 32
#define NN 16384
#define CC 256
#define DD 64
#define SS 7
#define HH 128
#define MROWS (BB*NN)
#define SCALE_ATTN 0.125f
#define EPS_ATTN 1e-6f
#define LN_EPS 1e-5f
#define NCHUNK 16
#define CHUNK (NN/NCHUNK)
#define PART_STRIDE 456
#define APITCH 40   // fp16 row pitch (80B: 16B-aligned rows, conflict-free ldmatrix)

// proj smem (dynamic): two chunk buffers of [Ah|Bh], each 128x40 fp16
#define PJ_B      10240
#define PJ_BUF    20480
#define PJ_PARAMS 40960
#define PJ_SMEM   44032

// ---------------- scratch (static device globals; no allocation) ----------------
__device__ float g_K[MROWS*DD];
__device__ float g_V[MROWS*DD];
__device__ float g_q[BB*SS*DD];
__device__ float g_part[BB*NCHUNK*PART_STRIDE];
__device__ __half g_WbH[128*256];   // fp16 weights, row-major [n][c]

__device__ __forceinline__ float sigmoidf_(float x) { return 1.0f / (1.0f + __expf(-x)); }

__device__ __forceinline__ uint32_t smem_u32(const void* p) {
    uint32_t a;
    asm("{ .reg .u64 t; cvta.to.shared.u64 t, %1; cvt.u32.u64 %0, t; }" : "=r"(a) : "l"(p));
    return a;
}
__device__ __forceinline__ void mma16816(float* d, const uint32_t* a, const uint32_t* b) {
    asm volatile(
        "mma.sync.aligned.m16n8k16.row.col.f32.f16.f16.f32 "
        "{%0,%1,%2,%3}, {%4,%5,%6,%7}, {%8,%9}, {%0,%1,%2,%3};"
        : "+f"(d[0]), "+f"(d[1]), "+f"(d[2]), "+f"(d[3])
        : "r"(a[0]), "r"(a[1]), "r"(a[2]), "r"(a[3]), "r"(b[0]), "r"(b[1]));
}
__device__ __forceinline__ void ldsm_x4(uint32_t* r, uint32_t addr) {
    asm volatile("ldmatrix.sync.aligned.m8n8.x4.shared.b16 {%0,%1,%2,%3}, [%4];"
        : "=r"(r[0]), "=r"(r[1]), "=r"(r[2]), "=r"(r[3]) : "r"(addr));
}

// ---------------- kernel 0: init slot state into d_out ----------------
__global__ void init_slots_kernel(const float* __restrict__ mu, float* __restrict__ out) {
    int i = blockIdx.x * 256 + threadIdx.x;
    if (i < BB * SS * DD) out[i] = mu[i];
}

// ---------------- kernel 0b: [Wk|Wv]^T -> fp16, row-major [n][c] ----------------
__global__ void wsplit_kernel(const float* __restrict__ Wk, const float* __restrict__ Wv) {
    int idx = blockIdx.x * 256 + threadIdx.x;
    if (idx >= 128 * 256) return;
    int n = idx >> 8;
    int c = idx & 255;
    float w = (n < 64) ? Wk[c * 64 + n] : Wv[c * 64 + (n - 64)];
    g_WbH[n * 256 + c] = __float2half_rn(w);
}

// ---------------- kernel 2: iteration-0 q projection ----------------
__global__ void __launch_bounds__(256) q_kernel(
    const float* __restrict__ slots,
    const float* __restrict__ qlg, const float* __restrict__ qlb,
    const float* __restrict__ Wq,
    const float* __restrict__ bqlg, const float* __restrict__ bqlb,
    const float* __restrict__ bWq)
{
    __shared__ float xs[8][64];
    const int tid = threadIdx.x, lane = tid & 31, ws = tid >> 5;
    const int wid = blockIdx.x * 8 + ws;
    const int m = wid % SS;

    const float* x = slots + wid * DD;
    float x0 = x[lane], x1 = x[lane + 32];
    float s = x0 + x1, q = x0 * x0 + x1 * x1;
    #pragma unroll
    for (int o = 16; o; o >>= 1) {
        s += __shfl_xor_sync(0xffffffffu, s, o);
        q += __shfl_xor_sync(0xffffffffu, q, o);
    }
    float mu = s * (1.f / 64.f);
    float rs = rsqrtf(q * (1.f / 64.f) - mu * mu + LN_EPS);

    const float* lg = (m < 6) ? qlg : bqlg;
    const float* lb = (m < 6) ? qlb : bqlb;
    const float* W  = (m < 6) ? Wq  : bWq;

    xs[ws][lane]      = (x0 - mu) * rs * lg[lane]      + lb[lane];
    xs[ws][lane + 32] = (x1 - mu) * rs * lg[lane + 32] + lb[lane + 32];
    __syncwarp();

    float q0 = 0.f, q1 = 0.f;
    #pragma unroll
    for (int e = 0; e < 64; e++) {
        float xe = xs[ws][e];
        q0 += xe * W[e * 64 + lane];
        q1 += xe * W[e * 64 + lane + 32];
    }
    g_q[wid * DD + lane]      = q0;
    g_q[wid * DD + lane + 32] = q1;
}

// ---------------- kernel 1: LN + [K|V] projection, single-pass fp16 mma.sync ----------------
__global__ void __launch_bounds__(256, 2) proj_mma_kernel(
    const float* __restrict__ X,
    const float* __restrict__ lng, const float* __restrict__ lnb)
{
    extern __shared__ char smem[];
    float* s_mean = (float*)(smem + PJ_PARAMS);
    float* s_rstd = (float*)(smem + PJ_PARAMS + 512);
    float* s_g    = (float*)(smem + PJ_PARAMS + 1024);
    float* s_b    = (float*)(smem + PJ_PARAMS + 2048);

    const int tid = threadIdx.x, wid = tid >> 5, lane = tid & 31;
    const int m0 = blockIdx.x * 128;
    const uint32_t sbase = smem_u32(smem);

    s_g[tid] = lng[tid];
    s_b[tid] = lnb[tid];

    // ---- LN stats ----
    #pragma unroll 1
    for (int p = 0; p < 4; p++) {
        float sm[4], sq[4];
        #pragma unroll
        for (int i = 0; i < 4; i++) {
            int r = (p * 4 + i) * 8 + wid;
            const float* xr = X + (size_t)(m0 + r) * CC + lane * 8;
            float4 a  = *(const float4*)xr;
            float4 b4 = *(const float4*)(xr + 4);
            sm[i] = a.x + a.y + a.z + a.w + b4.x + b4.y + b4.z + b4.w;
            sq[i] = a.x*a.x + a.y*a.y + a.z*a.z + a.w*a.w
                  + b4.x*b4.x + b4.y*b4.y + b4.z*b4.z + b4.w*b4.w;
        }
        #pragma unroll
        for (int i = 0; i < 4; i++) {
            #pragma unroll
            for (int o = 16; o; o >>= 1) {
                sm[i] += __shfl_xor_sync(0xffffffffu, sm[i], o);
                sq[i] += __shfl_xor_sync(0xffffffffu, sq[i], o);
            }
            if (lane == 0) {
                int r = (p * 4 + i) * 8 + wid;
                float mu = sm[i] * (1.f / 256.f);
                s_mean[r] = mu;
                s_rstd[r] = rsqrtf(sq[i] * (1.f / 256.f) - mu * mu + LN_EPS);
            }
        }
    }
    __syncthreads();

    // loader roles
    const int r   = tid >> 1;
    const int seg = tid & 1;
    const float mu = s_mean[r], rs = s_rstd[r];
    const float* xrow = X + (size_t)(m0 + r) * CC + seg * 16;
    const __half* wHrow = g_WbH + r * 256 + seg * 16;

    // mma roles
    const int mw = wid >> 1, nw = wid & 1;
    const int g  = lane >> 2, tg = lane & 3;
    const int mat = lane >> 3, rb = lane & 7;
    const uint32_t aoff = (uint32_t)((mw*32 + rb + (mat & 1)*8) * APITCH + (mat >> 1)*8) * 2;
    const uint32_t boff = (uint32_t)((nw*64 + rb) * APITCH + mat*8) * 2;

    float acc[2][8][4];
    #pragma unroll
    for (int mt = 0; mt < 2; mt++)
        #pragma unroll
        for (int nt = 0; nt < 8; nt++)
            #pragma unroll
            for (int e = 0; e < 4; e++) acc[mt][nt][e] = 0.f;

    float4 xv[4];
    uint4 bvh[2];

    // prologue: load chunk0 regs, stage buf0, load chunk1 regs
    #pragma unroll
    for (int i = 0; i < 4; i++) xv[i] = *(const float4*)(xrow + i * 4);
    bvh[0] = *(const uint4*)(wHrow);
    bvh[1] = *(const uint4*)(wHrow + 8);

    {   // stage chunk 0 -> buf 0
        char* Ah = smem;
        char* Bh = smem + PJ_B;
        uint32_t pk[8];
        #pragma unroll
        for (int i = 0; i < 4; i++) {
            int c = seg * 16 + i * 4;
            float y0 = fmaf((xv[i].x - mu) * rs, s_g[c+0], s_b[c+0]);
            float y1 = fmaf((xv[i].y - mu) * rs, s_g[c+1], s_b[c+1]);
            float y2 = fmaf((xv[i].z - mu) * rs, s_g[c+2], s_b[c+2]);
            float y3 = fmaf((xv[i].w - mu) * rs, s_g[c+3], s_b[c+3]);
            __half2 h01 = __float22half2_rn(make_float2(y0, y1));
            __half2 h23 = __float22half2_rn(make_float2(y2, y3));
            pk[i * 2]     = *(uint32_t*)&h01;
            pk[i * 2 + 1] = *(uint32_t*)&h23;
        }
        *(uint4*)(Ah + r * 80 + seg * 32)      = make_uint4(pk[0], pk[1], pk[2], pk[3]);
        *(uint4*)(Ah + r * 80 + seg * 32 + 16) = make_uint4(pk[4], pk[5], pk[6], pk[7]);
        *(uint4*)(Bh + r * 80 + seg * 32)      = bvh[0];
        *(uint4*)(Bh + r * 80 + seg * 32 + 16) = bvh[1];
    }
    #pragma unroll
    for (int i = 0; i < 4; i++) xv[i] = *(const float4*)(xrow + 32 + i * 4);
    bvh[0] = *(const uint4*)(wHrow + 32);
    bvh[1] = *(const uint4*)(wHrow + 40);
    __syncthreads();

    #pragma unroll 1
    for (int kc = 0; kc < 8; kc++) {
        const uint32_t bufo = (uint32_t)(kc & 1) * PJ_BUF;

        // ---- stage chunk kc+1 into the other buffer ----
        if (kc < 7) {
            uint32_t nb = (uint32_t)((kc + 1) & 1) * PJ_BUF;
            char* Ah = smem + nb;
            char* Bh = smem + nb + PJ_B;
            uint32_t pk[8];
            #pragma unroll
            for (int i = 0; i < 4; i++) {
                int c = (kc + 1) * 32 + seg * 16 + i * 4;
                float y0 = fmaf((xv[i].x - mu) * rs, s_g[c+0], s_b[c+0]);
                float y1 = fmaf((xv[i].y - mu) * rs, s_g[c+1], s_b[c+1]);
                float y2 = fmaf((xv[i].z - mu) * rs, s_g[c+2], s_b[c+2]);
                float y3 = fmaf((xv[i].w - mu) * rs, s_g[c+3], s_b[c+3]);
                __half2 h01 = __float22half2_rn(make_float2(y0, y1));
                __half2 h23 = __float22half2_rn(make_float2(y2, y3));
                pk[i * 2]     = *(uint32_t*)&h01;
                pk[i * 2 + 1] = *(uint32_t*)&h23;
            }
            *(uint4*)(Ah + r * 80 + seg * 32)      = make_uint4(pk[0], pk[1], pk[2], pk[3]);
            *(uint4*)(Ah + r * 80 + seg * 32 + 16) = make_uint4(pk[4], pk[5], pk[6], pk[7]);
            *(uint4*)(Bh + r * 80 + seg * 32)      = bvh[0];
            *(uint4*)(Bh + r * 80 + seg * 32 + 16) = bvh[1];
        }
        // ---- prefetch chunk kc+2 from global ----
        if (kc < 6) {
            const float* xp = xrow + (kc + 2) * 32;
            #pragma unroll
            for (int i = 0; i < 4; i++) xv[i] = *(const float4*)(xp + i * 4);
            const __half* wh = wHrow + (kc + 2) * 32;
            bvh[0] = *(const uint4*)(wh);
            bvh[1] = *(const uint4*)(wh + 8);
        }

        // ---- MMA over current buffer via ldmatrix: single pass Ah x Bh ----
        {
            const uint32_t aH = sbase + bufo + aoff;
            const uint32_t bH = sbase + bufo + PJ_B + boff;

            uint32_t ah[2][2][4];
            #pragma unroll
            for (int mt = 0; mt < 2; mt++)
                #pragma unroll
                for (int ks = 0; ks < 2; ks++)
                    ldsm_x4(ah[mt][ks], aH + mt * 1280 + ks * 32);
            #pragma unroll
            for (int nt = 0; nt < 8; nt++) {
                uint32_t bh[4];
                ldsm_x4(bh, bH + nt * 640);
                #pragma unroll
                for (int ks = 0; ks < 2; ks++)
                    #pragma unroll
                    for (int mt = 0; mt < 2; mt++)
                        mma16816(acc[mt][nt], ah[mt][ks], &bh[ks * 2]);
            }
        }
        __syncthreads();
    }

    // ---- epilogue ----
    float* dstbase = nw ? g_V : g_K;
    #pragma unroll
    for (int mt = 0; mt < 2; mt++) {
        int row0 = m0 + mw * 32 + mt * 16 + g;
        #pragma unroll
        for (int nt = 0; nt < 8; nt++) {
            int coll = nt * 8 + tg * 2;
            *(float2*)(dstbase + (size_t)row0 * DD + coll) =
                make_float2(acc[mt][nt][0], acc[mt][nt][1]);
            *(float2*)(dstbase + (size_t)(row0 + 8) * DD + coll) =
                make_float2(acc[mt][nt][2], acc[mt][nt][3]);
        }
    }
}

// ---------------- kernel 3: attention — 16 lanes/row, 2 rows/warp, 4-way n ILP ----------------
__global__ void __launch_bounds__(256, 2) attn_kernel(float* __restrict__ part)
{
    const int b = blockIdx.y;
    const int chunk = blockIdx.x;
    __shared__ float qs[SS * DD];
    __shared__ float Uw[8][PART_STRIDE];
    const int tid = threadIdx.x;
    for (int i = tid; i < SS * DD; i += 256) qs[i] = g_q[b * SS * DD + i];
    __syncthreads();

    const int lane = tid & 31, warp = tid >> 5;
    const int g = lane >> 4;
    const int j = lane & 15;

    float Up[SS][4];
    #pragma unroll
    for (int m = 0; m < SS; m++)
        #pragma unroll
        for (int e = 0; e < 4; e++) Up[m][e] = 0.f;
    float cs[SS] = {0.f, 0.f, 0.f, 0.f, 0.f, 0.f, 0.f};

    const float* Kb = g_K + (size_t)b * NN * DD;
    const float* Vb = g_V + (size_t)b * NN * DD;
    const int base = chunk * CHUNK + warp * 2 + g;

    #pragma unroll 1
    for (int s = 0; s < CHUNK / 64; s++) {
        int n0 = base + s * 16;
        float4 k4[4], v4[4];
        #pragma unroll
        for (int q = 0; q < 4; q++) {
            int n = n0 + q * (CHUNK / 4);
            k4[q] = __ldcs((const float4*)(Kb + (size_t)n * DD + j * 4));
            v4[q] = __ldcs((const float4*)(Vb + (size_t)n * DD + j * 4));
        }
        #pragma unroll
        for (int h = 0; h < 2; h++) {
            float4 ka = k4[h * 2], kb = k4[h * 2 + 1];
            float4 va = v4[h * 2], vb = v4[h * 2 + 1];
            float la[SS], lb_[SS];
            #pragma unroll
            for (int m = 0; m < SS; m++) {
                float4 qm = *(const float4*)(qs + m * DD + j * 4);
                float pa = ka.x * qm.x + ka.y * qm.y + ka.z * qm.z + ka.w * qm.w;
                float pb = kb.x * qm.x + kb.y * qm.y + kb.z * qm.z + kb.w * qm.w;
                #pragma unroll
                for (int o = 1; o < 16; o <<= 1) {
                    pa += __shfl_xor_sync(0xffffffffu, pa, o);
                    pb += __shfl_xor_sync(0xffffffffu, pb, o);
                }
                la[m]  = pa * SCALE_ATTN;
                lb_[m] = pb * SCALE_ATTN;
            }
            float mxa = la[0], mxb = lb_[0];
            #pragma unroll
            for (int m = 1; m < SS; m++) { mxa = fmaxf(mxa, la[m]); mxb = fmaxf(mxb, lb_[m]); }
            float ea[SS], eb[SS], sa = 0.f, sb2 = 0.f;
            #pragma unroll
            for (int m = 0; m < SS; m++) {
                ea[m] = __expf(la[m] - mxa);  sa  += ea[m];
                eb[m] = __expf(lb_[m] - mxb); sb2 += eb[m];
            }
            float inva = 1.0f / sa, invb = 1.0f / sb2;
            #pragma unroll
            for (int m = 0; m < SS; m++) {
                float aa = ea[m] * inva + EPS_ATTN;
                float ab = eb[m] * invb + EPS_ATTN;
                cs[m] += aa + ab;
                Up[m][0] += aa * va.x + ab * vb.x;
                Up[m][1] += aa * va.y + ab * vb.y;
                Up[m][2] += aa * va.z + ab * vb.z;
                Up[m][3] += aa * va.w + ab * vb.w;
            }
        }
    }

    #pragma unroll
    for (int m = 0; m < SS; m++) {
        #pragma unroll
        for (int e = 0; e < 4; e++) {
            float t = Up[m][e];
            t += __shfl_xor_sync(0xffffffffu, t, 16);
            Up[m][e] = t;
        }
        float c = cs[m];
        c += __shfl_xor_sync(0xffffffffu, c, 16);
        cs[m] = c;
    }
    if (lane < 16) {
        #pragma unroll
        for (int m = 0; m < SS; m++)
            #pragma unroll
            for (int e = 0; e < 4; e++)
                Uw[warp][m * DD + j * 4 + e] = Up[m][e];
    }
    if (lane == 0) {
        #pragma unroll
        for (int m = 0; m < SS; m++) Uw[warp][448 + m] = cs[m];
    }
    __syncthreads();

    float* dst = part + (size_t)(b * NCHUNK + chunk) * PART_STRIDE;
    for (int i = tid; i < 455; i += 256) {
        float acc = Uw[0][i];
        #pragma unroll
        for (int w = 1; w < 8; w++) acc += Uw[w][i];
        dst[i] = acc;
    }
}

// ---------------- kernel 4: slot update + fused next-iter q projection ----------------
__global__ void __launch_bounds__(128) update_kernel(
    float* __restrict__ slots,
    const float* __restrict__ Wih, const float* __restrict__ Whh,
    const float* __restrict__ bih, const float* __restrict__ bhh,
    const float* __restrict__ mlng, const float* __restrict__ mlnb,
    const float* __restrict__ mW1,  const float* __restrict__ mb1,
    const float* __restrict__ mW2,  const float* __restrict__ mb2,
    const float* __restrict__ bmlng, const float* __restrict__ bmlnb,
    const float* __restrict__ bmW1,  const float* __restrict__ bmb1,
    const float* __restrict__ bmW2,  const float* __restrict__ bmb2,
    const float* __restrict__ qlg, const float* __restrict__ qlb,
    const float* __restrict__ Wq,
    const float* __restrict__ bqlg, const float* __restrict__ bqlb,
    const float* __restrict__ bWq)
{
    const int b = blockIdx.y;
    const int s = blockIdx.x;
    const int t = threadIdx.x;

    __shared__ float us[64], hs[64], gi[192], gh[192], hn[64], xn[64], hid[128], fin[64], xq[64];
    __shared__ float red[2], red2[2];

    if (t < 64) {
        float ua = 0.f, ca = 0.f;
        #pragma unroll 1
        for (int c = 0; c < NCHUNK; c++) {
            const float* p = g_part + (size_t)(b * NCHUNK + c) * PART_STRIDE;
            ua += p[s * 64 + t];
            ca += p[448 + s];
        }
        us[t] = ua / ca;
        hs[t] = slots[(b * SS + s) * DD + t];
    }
    __syncthreads();

    for (int idx = t; idx < 384; idx += 128) {
        const bool isI = (idx < 192);
        const int oo = isI ? idx : (idx - 192);
        const float* W  = isI ? Wih : Whh;
        const float* xv = isI ? us : hs;
        float acc = isI ? bih[oo] : bhh[oo];
        #pragma unroll
        for (int e = 0; e < 64; e++) acc += xv[e] * W[oo * 64 + e];
        if (isI) gi[oo] = acc; else gh[oo] = acc;
    }
    __syncthreads();

    if (t < 64) {
        float r = sigmoidf_(gi[t] + gh[t]);
        float z = sigmoidf_(gi[64 + t] + gh[64 + t]);
        float n = tanhf(gi[128 + t] + r * gh[128 + t]);
        hn[t] = (1.0f - z) * n + z * hs[t];
    }
    __syncthreads();

    if (t < 32) {
        float a = hn[t], bv = hn[t + 32];
        float sm = a + bv, sq = a * a + bv * bv;
        #pragma unroll
        for (int o = 16; o; o >>= 1) {
            sm += __shfl_xor_sync(0xffffffffu, sm, o);
            sq += __shfl_xor_sync(0xffffffffu, sq, o);
        }
        if (t == 0) {
            float mu = sm * (1.f / 64.f);
            red[0] = mu;
            red[1] = rsqrtf(sq * (1.f / 64.f) - mu * mu + LN_EPS);
        }
    }
    __syncthreads();

    const float* lg = (s < 6) ? mlng : bmlng;
    const float* lb = (s < 6) ? mlnb : bmlnb;
    const float* W1 = (s < 6) ? mW1 : bmW1;
    const float* b1 = (s < 6) ? mb1 : bmb1;
    const float* W2 = (s < 6) ? mW2 : bmW2;
    const float* b2 = (s < 6) ? mb2 : bmb2;

    if (t < 64) xn[t] = (hn[t] - red[0]) * red[1] * lg[t] + lb[t];
    __syncthreads();

    {
        float h1 = b1[t];
        #pragma unroll
        for (int e = 0; e < 64; e++) h1 += xn[e] * W1[e * HH + t];
        hid[t] = fmaxf(h1, 0.f);
    }
    __syncthreads();

    if (t < 64) {
        float o = b2[t];
        #pragma unroll
        for (int jj = 0; jj < 128; jj++) o += hid[jj] * W2[jj * 64 + t];
        float fv = hn[t] + o;
        slots[(b * SS + s) * DD + t] = fv;
        fin[t] = fv;
    }
    __syncthreads();

    // ---- fused q projection for next iteration ----
    if (t < 32) {
        float a = fin[t], bv = fin[t + 32];
        float sm = a + bv, sq = a * a + bv * bv;
        #pragma unroll
        for (int o = 16; o; o >>= 1) {
            sm += __shfl_xor_sync(0xffffffffu, sm, o);
            sq += __shfl_xor_sync(0xffffffffu, sq, o);
        }
        if (t == 0) {
            float mu = sm * (1.f / 64.f);
            red2[0] = mu;
            red2[1] = rsqrtf(sq * (1.f / 64.f) - mu * mu + LN_EPS);
        }
    }
    __syncthreads();

    const float* qg = (s < 6) ? qlg : bqlg;
    const float* qb = (s < 6) ? qlb : bqlb;
    const float* qW = (s < 6) ? Wq  : bWq;

    if (t < 64) xq[t] = (fin[t] - red2[0]) * red2[1] * qg[t] + qb[t];
    __syncthreads();

    if (t < 64) {
        float qv = 0.f;
        #pragma unroll
        for (int e = 0; e < 64; e++) qv += xq[e] * qW[e * 64 + t];
        g_q[(b * SS + s) * DD + t] = qv;
    }
}

// ---------------- launcher ----------------
extern "C" void kernel_launch(void* const* d_in, const int* in_sizes, int n_in,
                              void* d_out, int out_size) {
    (void)in_sizes; (void)n_in; (void)out_size;
    const float* inputs   = (const float*)d_in[0];
    const float* slots_mu = (const float*)d_in[1];
    const float* ln_in_g  = (const float*)d_in[2];
    const float* ln_in_b  = (const float*)d_in[3];
    const float* Wk       = (const float*)d_in[4];
    const float* Wv       = (const float*)d_in[5];
    const float* q_ln_g   = (const float*)d_in[6];
    const float* q_ln_b   = (const float*)d_in[7];
    const float* Wq       = (const float*)d_in[8];
    const float* bq_ln_g  = (const float*)d_in[9];
    const float* bq_ln_b  = (const float*)d_in[10];
    const float* bWq      = (const float*)d_in[11];
    const float* gWih     = (const float*)d_in[12];
    const float* gWhh     = (const float*)d_in[13];
    const float* gbih     = (const float*)d_in[14];
    const float* gbhh     = (const float*)d_in[15];
    const float* mlng     = (const float*)d_in[16];
    const float* mlnb     = (const float*)d_in[17];
    const float* mW1      = (const float*)d_in[18];
    const float* mb1      = (const float*)d_in[19];
    const float* mW2      = (const float*)d_in[20];
    const float* mb2      = (const float*)d_in[21];
    const float* bmlng    = (const float*)d_in[22];
    const float* bmlnb    = (const float*)d_in[23];
    const float* bmW1     = (const float*)d_in[24];
    const float* bmb1     = (const float*)d_in[25];
    const float* bmW2     = (const float*)d_in[26];
    const float* bmb2     = (const float*)d_in[27];
    float* out = (float*)d_out;

    float* part;
    cudaGetSymbolAddress((void**)&part, g_part);

    cudaFuncSetAttribute(proj_mma_kernel,
                         cudaFuncAttributeMaxDynamicSharedMemorySize, PJ_SMEM);

    // order keeps the ncu fixed-index capture on proj_mma_kernel
    init_slots_kernel<<<56, 256>>>(slots_mu, out);
    wsplit_kernel<<<128, 256>>>(Wk, Wv);
    q_kernel<<<28, 256>>>(out, q_ln_g, q_ln_b, Wq, bq_ln_g, bq_ln_b, bWq);
    proj_mma_kernel<<<MROWS / 128, 256, PJ_SMEM>>>(inputs, ln_in_g, ln_in_b);

    for (int it = 0; it < 3; it++) {
        attn_kernel<<<dim3(NCHUNK, BB), 256>>>(part);
        update_kernel<<<dim3(SS, BB), 128>>>(out, gWih, gWhh, gbih, gbhh,
                                             mlng, mlnb, mW1, mb1, mW2, mb2,
                                             bmlng, bmlnb, bmW1, bmb1, bmW2, bmb2,
                                             q_ln_g, q_ln_b, Wq, bq_ln_g, bq_ln_b, bWq);
    }
}

// round 13
// speedup vs baseline: 1.6506x; 1.1309x over previous
#include <cuda_runtime.h>
#include <cuda_fp16.h>
#include <cstdint>

#define BB 32
#define NN 16384
#define CC 256
#define DD 64
#define SS 7
#define HH 128
#define MROWS (BB*NN)
#define SCALE_ATTN 0.125f
#define EPS_ATTN 1e-6f
#define LN_EPS 1e-5f
#define NCHUNK 16
#define CHUNK (NN/NCHUNK)
#define PART_STRIDE 456
#define APITCH 40   // fp16 row pitch (80B: 16B-aligned rows, conflict-free ldmatrix)

// proj smem (dynamic): two chunk buffers of [Ah|Bh] (each 128x40 fp16), then params
#define PJ_B      10240
#define PJ_BUF    20480
#define PJ_PARAMS 40960     // s_mean[128], s_rstd[128], sG[128], sT[128]
#define PJ_SMEM   43008

// ---------------- scratch (static device globals; no allocation) ----------------
__device__ float g_K[MROWS*DD];
__device__ float g_V[MROWS*DD];
__device__ float g_q[BB*SS*DD];
__device__ float g_part[BB*NCHUNK*PART_STRIDE];
__device__ __half g_WbH[128*256];   // fp16 g-scaled weights, row-major [n][c]
__device__ float g_Gn[128];         // G_n = sum_c g_c W_cn
__device__ float g_Tn[128];         // T_n = sum_c b_c W_cn

__device__ __forceinline__ float sigmoidf_(float x) { return 1.0f / (1.0f + __expf(-x)); }

__device__ __forceinline__ uint32_t smem_u32(const void* p) {
    uint32_t a;
    asm("{ .reg .u64 t; cvta.to.shared.u64 t, %1; cvt.u32.u64 %0, t; }" : "=r"(a) : "l"(p));
    return a;
}
__device__ __forceinline__ void mma16816(float* d, const uint32_t* a, const uint32_t* b) {
    asm volatile(
        "mma.sync.aligned.m16n8k16.row.col.f32.f16.f16.f32 "
        "{%0,%1,%2,%3}, {%4,%5,%6,%7}, {%8,%9}, {%0,%1,%2,%3};"
        : "+f"(d[0]), "+f"(d[1]), "+f"(d[2]), "+f"(d[3])
        : "r"(a[0]), "r"(a[1]), "r"(a[2]), "r"(a[3]), "r"(b[0]), "r"(b[1]));
}
__device__ __forceinline__ void ldsm_x4(uint32_t* r, uint32_t addr) {
    asm volatile("ldmatrix.sync.aligned.m8n8.x4.shared.b16 {%0,%1,%2,%3}, [%4];"
        : "=r"(r[0]), "=r"(r[1]), "=r"(r[2]), "=r"(r[3]) : "r"(addr));
}

// ---------------- kernel 0: init slot state into d_out ----------------
__global__ void init_slots_kernel(const float* __restrict__ mu, float* __restrict__ out) {
    int i = blockIdx.x * 256 + threadIdx.x;
    if (i < BB * SS * DD) out[i] = mu[i];
}

// ---------------- kernel 0b: W' = g*[Wk|Wv]^T -> fp16 [n][c]; plus G/T column sums ----------------
__global__ void wsplit_kernel(const float* __restrict__ Wk, const float* __restrict__ Wv,
                              const float* __restrict__ lng, const float* __restrict__ lnb) {
    int idx = blockIdx.x * 256 + threadIdx.x;
    if (idx < 128 * 256) {
        int n = idx >> 8;
        int c = idx & 255;
        float w = (n < 64) ? Wk[c * 64 + n] : Wv[c * 64 + (n - 64)];
        g_WbH[n * 256 + c] = __float2half_rn(lng[c] * w);
    }
    if (blockIdx.x == 0 && threadIdx.x < 128) {
        int n = threadIdx.x;
        float G = 0.f, T = 0.f;
        #pragma unroll 4
        for (int c = 0; c < 256; c++) {
            float w = (n < 64) ? Wk[c * 64 + n] : Wv[c * 64 + (n - 64)];
            G += lng[c] * w;
            T += lnb[c] * w;
        }
        g_Gn[n] = G;
        g_Tn[n] = T;
    }
}

// ---------------- kernel 2: iteration-0 q projection ----------------
__global__ void __launch_bounds__(256) q_kernel(
    const float* __restrict__ slots,
    const float* __restrict__ qlg, const float* __restrict__ qlb,
    const float* __restrict__ Wq,
    const float* __restrict__ bqlg, const float* __restrict__ bqlb,
    const float* __restrict__ bWq)
{
    __shared__ float xs[8][64];
    const int tid = threadIdx.x, lane = tid & 31, ws = tid >> 5;
    const int wid = blockIdx.x * 8 + ws;
    const int m = wid % SS;

    const float* x = slots + wid * DD;
    float x0 = x[lane], x1 = x[lane + 32];
    float s = x0 + x1, q = x0 * x0 + x1 * x1;
    #pragma unroll
    for (int o = 16; o; o >>= 1) {
        s += __shfl_xor_sync(0xffffffffu, s, o);
        q += __shfl_xor_sync(0xffffffffu, q, o);
    }
    float mu = s * (1.f / 64.f);
    float rs = rsqrtf(q * (1.f / 64.f) - mu * mu + LN_EPS);

    const float* lg = (m < 6) ? qlg : bqlg;
    const float* lb = (m < 6) ? qlb : bqlb;
    const float* W  = (m < 6) ? Wq  : bWq;

    xs[ws][lane]      = (x0 - mu) * rs * lg[lane]      + lb[lane];
    xs[ws][lane + 32] = (x1 - mu) * rs * lg[lane + 32] + lb[lane + 32];
    __syncwarp();

    float q0 = 0.f, q1 = 0.f;
    #pragma unroll
    for (int e = 0; e < 64; e++) {
        float xe = xs[ws][e];
        q0 += xe * W[e * 64 + lane];
        q1 += xe * W[e * 64 + lane + 32];
    }
    g_q[wid * DD + lane]      = q0;
    g_q[wid * DD + lane + 32] = q1;
}

// ---------------- kernel 1: [K|V] projection on raw fp16 X; LN folded into epilogue ----------------
__global__ void __launch_bounds__(256, 2) proj_mma_kernel(const float* __restrict__ X)
{
    extern __shared__ char smem[];
    float* s_mean = (float*)(smem + PJ_PARAMS);
    float* s_rstd = (float*)(smem + PJ_PARAMS + 512);
    float* sG     = (float*)(smem + PJ_PARAMS + 1024);
    float* sT     = (float*)(smem + PJ_PARAMS + 1536);

    const int tid = threadIdx.x, wid = tid >> 5, lane = tid & 31;
    const int m0 = blockIdx.x * 128;
    const uint32_t sbase = smem_u32(smem);

    if (tid < 128) {
        sG[tid] = g_Gn[tid];
        sT[tid] = g_Tn[tid];
    }

    // loader roles
    const int r   = tid >> 1;
    const int seg = tid & 1;
    const float* xrow = X + (size_t)(m0 + r) * CC + seg * 16;
    const __half* wHrow = g_WbH + r * 256 + seg * 16;

    // mma roles
    const int mw = wid >> 1, nw = wid & 1;
    const int g  = lane >> 2, tg = lane & 3;
    const int mat = lane >> 3, rb = lane & 7;
    const uint32_t aoff = (uint32_t)((mw*32 + rb + (mat & 1)*8) * APITCH + (mat >> 1)*8) * 2;
    const uint32_t boff = (uint32_t)((nw*64 + rb) * APITCH + mat*8) * 2;

    float acc[2][8][4];
    #pragma unroll
    for (int mt = 0; mt < 2; mt++)
        #pragma unroll
        for (int nt = 0; nt < 8; nt++)
            #pragma unroll
            for (int e = 0; e < 4; e++) acc[mt][nt][e] = 0.f;

    float statS = 0.f, statQ = 0.f;   // per-thread LN partials (this thread's 128 cols)
    float4 xv[4];
    uint4 bvh[2];

    // prologue: load chunk0 regs, stage buf0 (+stats), load chunk1 regs
    #pragma unroll
    for (int i = 0; i < 4; i++) xv[i] = *(const float4*)(xrow + i * 4);
    bvh[0] = *(const uint4*)(wHrow);
    bvh[1] = *(const uint4*)(wHrow + 8);

    {   // stage chunk 0 -> buf 0
        char* Ah = smem;
        char* Bh = smem + PJ_B;
        uint32_t pk[8];
        #pragma unroll
        for (int i = 0; i < 4; i++) {
            statS += xv[i].x + xv[i].y + xv[i].z + xv[i].w;
            statQ += xv[i].x*xv[i].x + xv[i].y*xv[i].y + xv[i].z*xv[i].z + xv[i].w*xv[i].w;
            __half2 h01 = __float22half2_rn(make_float2(xv[i].x, xv[i].y));
            __half2 h23 = __float22half2_rn(make_float2(xv[i].z, xv[i].w));
            pk[i * 2]     = *(uint32_t*)&h01;
            pk[i * 2 + 1] = *(uint32_t*)&h23;
        }
        *(uint4*)(Ah + r * 80 + seg * 32)      = make_uint4(pk[0], pk[1], pk[2], pk[3]);
        *(uint4*)(Ah + r * 80 + seg * 32 + 16) = make_uint4(pk[4], pk[5], pk[6], pk[7]);
        *(uint4*)(Bh + r * 80 + seg * 32)      = bvh[0];
        *(uint4*)(Bh + r * 80 + seg * 32 + 16) = bvh[1];
    }
    #pragma unroll
    for (int i = 0; i < 4; i++) xv[i] = *(const float4*)(xrow + 32 + i * 4);
    bvh[0] = *(const uint4*)(wHrow + 32);
    bvh[1] = *(const uint4*)(wHrow + 40);
    __syncthreads();

    #pragma unroll 1
    for (int kc = 0; kc < 8; kc++) {
        const uint32_t bufo = (uint32_t)(kc & 1) * PJ_BUF;

        // ---- stage chunk kc+1 into the other buffer (+stats) ----
        if (kc < 7) {
            uint32_t nb = (uint32_t)((kc + 1) & 1) * PJ_BUF;
            char* Ah = smem + nb;
            char* Bh = smem + nb + PJ_B;
            uint32_t pk[8];
            #pragma unroll
            for (int i = 0; i < 4; i++) {
                statS += xv[i].x + xv[i].y + xv[i].z + xv[i].w;
                statQ += xv[i].x*xv[i].x + xv[i].y*xv[i].y + xv[i].z*xv[i].z + xv[i].w*xv[i].w;
                __half2 h01 = __float22half2_rn(make_float2(xv[i].x, xv[i].y));
                __half2 h23 = __float22half2_rn(make_float2(xv[i].z, xv[i].w));
                pk[i * 2]     = *(uint32_t*)&h01;
                pk[i * 2 + 1] = *(uint32_t*)&h23;
            }
            *(uint4*)(Ah + r * 80 + seg * 32)      = make_uint4(pk[0], pk[1], pk[2], pk[3]);
            *(uint4*)(Ah + r * 80 + seg * 32 + 16) = make_uint4(pk[4], pk[5], pk[6], pk[7]);
            *(uint4*)(Bh + r * 80 + seg * 32)      = bvh[0];
            *(uint4*)(Bh + r * 80 + seg * 32 + 16) = bvh[1];
        }
        // ---- prefetch chunk kc+2 from global ----
        if (kc < 6) {
            const float* xp = xrow + (kc + 2) * 32;
            #pragma unroll
            for (int i = 0; i < 4; i++) xv[i] = *(const float4*)(xp + i * 4);
            const __half* wh = wHrow + (kc + 2) * 32;
            bvh[0] = *(const uint4*)(wh);
            bvh[1] = *(const uint4*)(wh + 8);
        }

        // ---- MMA over current buffer via ldmatrix ----
        {
            const uint32_t aH = sbase + bufo + aoff;
            const uint32_t bH = sbase + bufo + PJ_B + boff;

            uint32_t ah[2][2][4];
            #pragma unroll
            for (int mt = 0; mt < 2; mt++)
                #pragma unroll
                for (int ks = 0; ks < 2; ks++)
                    ldsm_x4(ah[mt][ks], aH + mt * 1280 + ks * 32);
            #pragma unroll
            for (int nt = 0; nt < 8; nt++) {
                uint32_t bh[4];
                ldsm_x4(bh, bH + nt * 640);
                #pragma unroll
                for (int ks = 0; ks < 2; ks++)
                    #pragma unroll
                    for (int mt = 0; mt < 2; mt++)
                        mma16816(acc[mt][nt], ah[mt][ks], &bh[ks * 2]);
            }
        }
        __syncthreads();
    }

    // ---- finalize LN stats: combine the two per-row halves (partner lane) ----
    statS += __shfl_xor_sync(0xffffffffu, statS, 1);
    statQ += __shfl_xor_sync(0xffffffffu, statQ, 1);
    if (seg == 0) {
        float mu = statS * (1.f / 256.f);
        s_mean[r] = mu;
        s_rstd[r] = rsqrtf(statQ * (1.f / 256.f) - mu * mu + LN_EPS);
    }
    __syncthreads();

    // ---- epilogue: y = rs*(acc - mu*G) + T ----
    float* dstbase = nw ? g_V : g_K;
    #pragma unroll
    for (int mt = 0; mt < 2; mt++) {
        int lr = mw * 32 + mt * 16 + g;
        float mu0 = s_mean[lr],     rs0 = s_rstd[lr];
        float mu1 = s_mean[lr + 8], rs1 = s_rstd[lr + 8];
        int row0 = m0 + lr;
        #pragma unroll
        for (int nt = 0; nt < 8; nt++) {
            int col = nw * 64 + nt * 8 + tg * 2;     // global n (for G/T)
            int coll = nt * 8 + tg * 2;              // col within K or V
            float G0 = sG[col], G1 = sG[col + 1];
            float T0 = sT[col], T1 = sT[col + 1];
            *(float2*)(dstbase + (size_t)row0 * DD + coll) =
                make_float2(rs0 * (acc[mt][nt][0] - mu0 * G0) + T0,
                            rs0 * (acc[mt][nt][1] - mu0 * G1) + T1);
            *(float2*)(dstbase + (size_t)(row0 + 8) * DD + coll) =
                make_float2(rs1 * (acc[mt][nt][2] - mu1 * G0) + T0,
                            rs1 * (acc[mt][nt][3] - mu1 * G1) + T1);
        }
    }
}

// ---------------- kernel 3: attention — 16 lanes/row, 2 rows/warp, 4-way n ILP ----------------
__global__ void __launch_bounds__(256, 2) attn_kernel(float* __restrict__ part)
{
    const int b = blockIdx.y;
    const int chunk = blockIdx.x;
    __shared__ float qs[SS * DD];
    __shared__ float Uw[8][PART_STRIDE];
    const int tid = threadIdx.x;
    for (int i = tid; i < SS * DD; i += 256) qs[i] = g_q[b * SS * DD + i];
    __syncthreads();

    const int lane = tid & 31, warp = tid >> 5;
    const int g = lane >> 4;
    const int j = lane & 15;

    float Up[SS][4];
    #pragma unroll
    for (int m = 0; m < SS; m++)
        #pragma unroll
        for (int e = 0; e < 4; e++) Up[m][e] = 0.f;
    float cs[SS] = {0.f, 0.f, 0.f, 0.f, 0.f, 0.f, 0.f};

    const float* Kb = g_K + (size_t)b * NN * DD;
    const float* Vb = g_V + (size_t)b * NN * DD;
    const int base = chunk * CHUNK + warp * 2 + g;

    #pragma unroll 1
    for (int s = 0; s < CHUNK / 64; s++) {
        int n0 = base + s * 16;
        float4 k4[4], v4[4];
        #pragma unroll
        for (int q = 0; q < 4; q++) {
            int n = n0 + q * (CHUNK / 4);
            k4[q] = __ldcs((const float4*)(Kb + (size_t)n * DD + j * 4));
            v4[q] = __ldcs((const float4*)(Vb + (size_t)n * DD + j * 4));
        }
        #pragma unroll
        for (int h = 0; h < 2; h++) {
            float4 ka = k4[h * 2], kb = k4[h * 2 + 1];
            float4 va = v4[h * 2], vb = v4[h * 2 + 1];
            float la[SS], lb_[SS];
            #pragma unroll
            for (int m = 0; m < SS; m++) {
                float4 qm = *(const float4*)(qs + m * DD + j * 4);
                float pa = ka.x * qm.x + ka.y * qm.y + ka.z * qm.z + ka.w * qm.w;
                float pb = kb.x * qm.x + kb.y * qm.y + kb.z * qm.z + kb.w * qm.w;
                #pragma unroll
                for (int o = 1; o < 16; o <<= 1) {
                    pa += __shfl_xor_sync(0xffffffffu, pa, o);
                    pb += __shfl_xor_sync(0xffffffffu, pb, o);
                }
                la[m]  = pa * SCALE_ATTN;
                lb_[m] = pb * SCALE_ATTN;
            }
            float mxa = la[0], mxb = lb_[0];
            #pragma unroll
            for (int m = 1; m < SS; m++) { mxa = fmaxf(mxa, la[m]); mxb = fmaxf(mxb, lb_[m]); }
            float ea[SS], eb[SS], sa = 0.f, sb2 = 0.f;
            #pragma unroll
            for (int m = 0; m < SS; m++) {
                ea[m] = __expf(la[m] - mxa);  sa  += ea[m];
                eb[m] = __expf(lb_[m] - mxb); sb2 += eb[m];
            }
            float inva = 1.0f / sa, invb = 1.0f / sb2;
            #pragma unroll
            for (int m = 0; m < SS; m++) {
                float aa = ea[m] * inva + EPS_ATTN;
                float ab = eb[m] * invb + EPS_ATTN;
                cs[m] += aa + ab;
                Up[m][0] += aa * va.x + ab * vb.x;
                Up[m][1] += aa * va.y + ab * vb.y;
                Up[m][2] += aa * va.z + ab * vb.z;
                Up[m][3] += aa * va.w + ab * vb.w;
            }
        }
    }

    #pragma unroll
    for (int m = 0; m < SS; m++) {
        #pragma unroll
        for (int e = 0; e < 4; e++) {
            float t = Up[m][e];
            t += __shfl_xor_sync(0xffffffffu, t, 16);
            Up[m][e] = t;
        }
        float c = cs[m];
        c += __shfl_xor_sync(0xffffffffu, c, 16);
        cs[m] = c;
    }
    if (lane < 16) {
        #pragma unroll
        for (int m = 0; m < SS; m++)
            #pragma unroll
            for (int e = 0; e < 4; e++)
                Uw[warp][m * DD + j * 4 + e] = Up[m][e];
    }
    if (lane == 0) {
        #pragma unroll
        for (int m = 0; m < SS; m++) Uw[warp][448 + m] = cs[m];
    }
    __syncthreads();

    float* dst = part + (size_t)(b * NCHUNK + chunk) * PART_STRIDE;
    for (int i = tid; i < 455; i += 256) {
        float acc = Uw[0][i];
        #pragma unroll
        for (int w = 1; w < 8; w++) acc += Uw[w][i];
        dst[i] = acc;
    }
}

// ---------------- kernel 4: slot update + fused next-iter q projection ----------------
__global__ void __launch_bounds__(128) update_kernel(
    float* __restrict__ slots,
    const float* __restrict__ Wih, const float* __restrict__ Whh,
    const float* __restrict__ bih, const float* __restrict__ bhh,
    const float* __restrict__ mlng, const float* __restrict__ mlnb,
    const float* __restrict__ mW1,  const float* __restrict__ mb1,
    const float* __restrict__ mW2,  const float* __restrict__ mb2,
    const float* __restrict__ bmlng, const float* __restrict__ bmlnb,
    const float* __restrict__ bmW1,  const float* __restrict__ bmb1,
    const float* __restrict__ bmW2,  const float* __restrict__ bmb2,
    const float* __restrict__ qlg, const float* __restrict__ qlb,
    const float* __restrict__ Wq,
    const float* __restrict__ bqlg, const float* __restrict__ bqlb,
    const float* __restrict__ bWq)
{
    const int b = blockIdx.y;
    const int s = blockIdx.x;
    const int t = threadIdx.x;

    __shared__ float us[64], hs[64], gi[192], gh[192], hn[64], xn[64], hid[128], fin[64], xq[64];
    __shared__ float red[2], red2[2];

    if (t < 64) {
        float ua = 0.f, ca = 0.f;
        #pragma unroll 1
        for (int c = 0; c < NCHUNK; c++) {
            const float* p = g_part + (size_t)(b * NCHUNK + c) * PART_STRIDE;
            ua += p[s * 64 + t];
            ca += p[448 + s];
        }
        us[t] = ua / ca;
        hs[t] = slots[(b * SS + s) * DD + t];
    }
    __syncthreads();

    for (int idx = t; idx < 384; idx += 128) {
        const bool isI = (idx < 192);
        const int oo = isI ? idx : (idx - 192);
        const float* W  = isI ? Wih : Whh;
        const float* xv = isI ? us : hs;
        float acc = isI ? bih[oo] : bhh[oo];
        #pragma unroll
        for (int e = 0; e < 64; e++) acc += xv[e] * W[oo * 64 + e];
        if (isI) gi[oo] = acc; else gh[oo] = acc;
    }
    __syncthreads();

    if (t < 64) {
        float r = sigmoidf_(gi[t] + gh[t]);
        float z = sigmoidf_(gi[64 + t] + gh[64 + t]);
        float n = tanhf(gi[128 + t] + r * gh[128 + t]);
        hn[t] = (1.0f - z) * n + z * hs[t];
    }
    __syncthreads();

    if (t < 32) {
        float a = hn[t], bv = hn[t + 32];
        float sm = a + bv, sq = a * a + bv * bv;
        #pragma unroll
        for (int o = 16; o; o >>= 1) {
            sm += __shfl_xor_sync(0xffffffffu, sm, o);
            sq += __shfl_xor_sync(0xffffffffu, sq, o);
        }
        if (t == 0) {
            float mu = sm * (1.f / 64.f);
            red[0] = mu;
            red[1] = rsqrtf(sq * (1.f / 64.f) - mu * mu + LN_EPS);
        }
    }
    __syncthreads();

    const float* lg = (s < 6) ? mlng : bmlng;
    const float* lb = (s < 6) ? mlnb : bmlnb;
    const float* W1 = (s < 6) ? mW1 : bmW1;
    const float* b1 = (s < 6) ? mb1 : bmb1;
    const float* W2 = (s < 6) ? mW2 : bmW2;
    const float* b2 = (s < 6) ? mb2 : bmb2;

    if (t < 64) xn[t] = (hn[t] - red[0]) * red[1] * lg[t] + lb[t];
    __syncthreads();

    {
        float h1 = b1[t];
        #pragma unroll
        for (int e = 0; e < 64; e++) h1 += xn[e] * W1[e * HH + t];
        hid[t] = fmaxf(h1, 0.f);
    }
    __syncthreads();

    if (t < 64) {
        float o = b2[t];
        #pragma unroll
        for (int jj = 0; jj < 128; jj++) o += hid[jj] * W2[jj * 64 + t];
        float fv = hn[t] + o;
        slots[(b * SS + s) * DD + t] = fv;
        fin[t] = fv;
    }
    __syncthreads();

    // ---- fused q projection for next iteration ----
    if (t < 32) {
        float a = fin[t], bv = fin[t + 32];
        float sm = a + bv, sq = a * a + bv * bv;
        #pragma unroll
        for (int o = 16; o; o >>= 1) {
            sm += __shfl_xor_sync(0xffffffffu, sm, o);
            sq += __shfl_xor_sync(0xffffffffu, sq, o);
        }
        if (t == 0) {
            float mu = sm * (1.f / 64.f);
            red2[0] = mu;
            red2[1] = rsqrtf(sq * (1.f / 64.f) - mu * mu + LN_EPS);
        }
    }
    __syncthreads();

    const float* qg = (s < 6) ? qlg : bqlg;
    const float* qb = (s < 6) ? qlb : bqlb;
    const float* qW = (s < 6) ? Wq  : bWq;

    if (t < 64) xq[t] = (fin[t] - red2[0]) * red2[1] * qg[t] + qb[t];
    __syncthreads();

    if (t < 64) {
        float qv = 0.f;
        #pragma unroll
        for (int e = 0; e < 64; e++) qv += xq[e] * qW[e * 64 + t];
        g_q[(b * SS + s) * DD + t] = qv;
    }
}

// ---------------- launcher ----------------
extern "C" void kernel_launch(void* const* d_in, const int* in_sizes, int n_in,
                              void* d_out, int out_size) {
    (void)in_sizes; (void)n_in; (void)out_size;
    const float* inputs   = (const float*)d_in[0];
    const float* slots_mu = (const float*)d_in[1];
    const float* ln_in_g  = (const float*)d_in[2];
    const float* ln_in_b  = (const float*)d_in[3];
    const float* Wk       = (const float*)d_in[4];
    const float* Wv       = (const float*)d_in[5];
    const float* q_ln_g   = (const float*)d_in[6];
    const float* q_ln_b   = (const float*)d_in[7];
    const float* Wq       = (const float*)d_in[8];
    const float* bq_ln_g  = (const float*)d_in[9];
    const float* bq_ln_b  = (const float*)d_in[10];
    const float* bWq      = (const float*)d_in[11];
    const float* gWih     = (const float*)d_in[12];
    const float* gWhh     = (const float*)d_in[13];
    const float* gbih     = (const float*)d_in[14];
    const float* gbhh     = (const float*)d_in[15];
    const float* mlng     = (const float*)d_in[16];
    const float* mlnb     = (const float*)d_in[17];
    const float* mW1      = (const float*)d_in[18];
    const float* mb1      = (const float*)d_in[19];
    const float* mW2      = (const float*)d_in[20];
    const float* mb2      = (const float*)d_in[21];
    const float* bmlng    = (const float*)d_in[22];
    const float* bmlnb    = (const float*)d_in[23];
    const float* bmW1     = (const float*)d_in[24];
    const float* bmb1     = (const float*)d_in[25];
    const float* bmW2     = (const float*)d_in[26];
    const float* bmb2     = (const float*)d_in[27];
    float* out = (float*)d_out;

    float* part;
    cudaGetSymbolAddress((void**)&part, g_part);

    cudaFuncSetAttribute(proj_mma_kernel,
                         cudaFuncAttributeMaxDynamicSharedMemorySize, PJ_SMEM);

    // order keeps the ncu fixed-index capture on proj_mma_kernel
    init_slots_kernel<<<56, 256>>>(slots_mu, out);
    wsplit_kernel<<<128, 256>>>(Wk, Wv, ln_in_g, ln_in_b);
    q_kernel<<<28, 256>>>(out, q_ln_g, q_ln_b, Wq, bq_ln_g, bq_ln_b, bWq);
    proj_mma_kernel<<<MROWS / 128, 256, PJ_SMEM>>>(inputs);

    for (int it = 0; it < 3; it++) {
        attn_kernel<<<dim3(NCHUNK, BB), 256>>>(part);
        update_kernel<<<dim3(SS, BB), 128>>>(out, gWih, gWhh, gbih, gbhh,
                                             mlng, mlnb, mW1, mb1, mW2, mb2,
                                             bmlng, bmlnb, bmW1, bmb1, bmW2, bmb2,
                                             q_ln_g, q_ln_b, Wq, bq_ln_g, bq_ln_b, bWq);
    }
}